// round 2
// baseline (speedup 1.0000x reference)
#include <cuda_runtime.h>
#include <math.h>

// ---------------------------------------------------------------------------
// Problem constants
// ---------------------------------------------------------------------------
#define BB    2
#define TT    32
#define LLE   64
#define DD    1024
#define HH    16
#define HD    64
#define NWIN  8      // B * (T/WS)
#define SSQ   512    // WS * L
#define AROWS 4096   // NWIN * SSQ
#define TLTOK 2048   // T * L
#define BTLR  4096   // B * T * L
#define DG    2048   // 2*D
#define K3D   3072   // 3*D

// ---------------------------------------------------------------------------
// Scratch (static device globals — no allocations allowed)
// ---------------------------------------------------------------------------
__device__ float g_Q[NWIN * HH * SSQ * HD];
__device__ float g_K[NWIN * HH * SSQ * HD];
__device__ float g_V[NWIN * HH * SSQ * HD];
__device__ float g_O[(size_t)AROWS * DD];
__device__ float g_feats[(size_t)3 * BTLR * DD];
__device__ float g_G[(size_t)BTLR * DG];

__device__ __forceinline__ float gelu_f(float x) {
    return 0.5f * x * (1.0f + erff(x * 0.70710678118654752440f));
}

// ---------------------------------------------------------------------------
// Generic 128x128x8 double-buffered SGEMM, 256 threads, 8x8 microtile.
// MODE 0: QKV projection.  A = roll-gathered modality [B,T,L,D] rows.
//         C scatter -> g_Q/g_K/g_V in [NWIN][H][S][HD] layout (+bias).
// MODE 1: out projection.  A = g_O rows. Epilogue: +bias, +residual (gathered
//         at rolled-back location), write feats[which] in [B][T*L][D].
// MODE 2: gate MLP layer 1. A = concat(feats) gathered per-k. Epilogue:
//         gelu(x+bias) -> g_G.
// ---------------------------------------------------------------------------
template<int MODE>
__device__ __forceinline__ float4 gemm_loadA(const float* __restrict__ arow,
                                             int m0, int ra, int ka, int k0)
{
    if (MODE == 2) {
        int kk = k0 + ka;
        return *(const float4*)(g_feats
              + (((size_t)(kk >> 10) * BTLR + (size_t)(m0 + ra)) << 10)
              + (kk & 1023));
    } else {
        return *(const float4*)(arow + k0 + ka);
    }
}

template<int MODE>
__global__ __launch_bounds__(256) void gemm_k(
    const float* __restrict__ A0,     // MODE0: modality src; else unused
    const float* __restrict__ Bm,     // weight [K][N] row-major
    const float* __restrict__ bias,   // [N]
    const float* __restrict__ resid,  // MODE1: modality src for residual
    int which, int K, int N)
{
    __shared__ float As[2][8][132];
    __shared__ float Bs[2][8][132];

    const int tid = threadIdx.x;
    const int tx = tid & 15, ty = tid >> 4;
    const int m0 = blockIdx.y << 7, n0 = blockIdx.x << 7;

    const int ra = tid >> 1;           // A-load row in tile (0..127)
    const int ka = (tid & 1) << 2;     // A-load k offset (0 or 4)
    const int kb = tid >> 5;           // B-load k row (0..7)
    const int nb = (tid & 31) << 2;    // B-load n offset

    const float* arow = nullptr;
    if (MODE == 0) {
        int r = m0 + ra;
        int bw = r >> 9, s = r & 511;
        int b = bw >> 2, w = bw & 3;
        int st = s >> 6, l = s & 63;
        int t = (w * 8 + st + 4) & 31;            // roll(-SH) gather
        arow = A0 + ((size_t)((b * TT + t) * LLE + l) << 10);
    } else if (MODE == 1) {
        arow = g_O + ((size_t)(m0 + ra) << 10);
    }

    float acc[8][8];
    #pragma unroll
    for (int i = 0; i < 8; i++)
        #pragma unroll
        for (int j = 0; j < 8; j++) acc[i][j] = 0.f;

    const int nt = K >> 3;
    float4 pa = gemm_loadA<MODE>(arow, m0, ra, ka, 0);
    float4 pb = *(const float4*)(Bm + (size_t)kb * N + n0 + nb);

    int buf = 0;
    As[0][ka + 0][ra] = pa.x; As[0][ka + 1][ra] = pa.y;
    As[0][ka + 2][ra] = pa.z; As[0][ka + 3][ra] = pa.w;
    *(float4*)&Bs[0][kb][nb] = pb;
    __syncthreads();

    for (int t = 0; t < nt; t++) {
        if (t + 1 < nt) {
            int k0 = (t + 1) << 3;
            pa = gemm_loadA<MODE>(arow, m0, ra, ka, k0);
            pb = *(const float4*)(Bm + (size_t)(k0 + kb) * N + n0 + nb);
        }
        #pragma unroll
        for (int k = 0; k < 8; k++) {
            float4 a0 = *(const float4*)&As[buf][k][ty * 4];
            float4 a1 = *(const float4*)&As[buf][k][64 + ty * 4];
            float4 b0 = *(const float4*)&Bs[buf][k][tx * 4];
            float4 b1 = *(const float4*)&Bs[buf][k][64 + tx * 4];
            float av[8] = {a0.x, a0.y, a0.z, a0.w, a1.x, a1.y, a1.z, a1.w};
            float bv[8] = {b0.x, b0.y, b0.z, b0.w, b1.x, b1.y, b1.z, b1.w};
            #pragma unroll
            for (int i = 0; i < 8; i++)
                #pragma unroll
                for (int j = 0; j < 8; j++)
                    acc[i][j] = fmaf(av[i], bv[j], acc[i][j]);
        }
        if (t + 1 < nt) {
            buf ^= 1;
            As[buf][ka + 0][ra] = pa.x; As[buf][ka + 1][ra] = pa.y;
            As[buf][ka + 2][ra] = pa.z; As[buf][ka + 3][ra] = pa.w;
            *(float4*)&Bs[buf][kb][nb] = pb;
            __syncthreads();
        }
    }

    float* Cp;
    if (MODE == 0)      Cp = (which == 0) ? g_Q : (which == 1) ? g_K : g_V;
    else if (MODE == 1) Cp = g_feats + (size_t)which * BTLR * DD;
    else                Cp = g_G;

    #pragma unroll
    for (int iq = 0; iq < 2; iq++)
    #pragma unroll
    for (int ii = 0; ii < 4; ii++) {
        const int i = iq * 4 + ii;
        const int m = m0 + iq * 64 + ty * 4 + ii;
        int bw = m >> 9, s = m & 511;
        int b = bw >> 2, w = bw & 3;
        int st = s >> 6, l = s & 63;
        int tg = (w * 8 + st + 4) & 31;           // roll(+SH) scatter (same map)
        #pragma unroll
        for (int jq = 0; jq < 2; jq++) {
            const int n = n0 + jq * 64 + (tx << 2);
            float4 v;
            v.x = acc[i][jq * 4 + 0] + bias[n + 0];
            v.y = acc[i][jq * 4 + 1] + bias[n + 1];
            v.z = acc[i][jq * 4 + 2] + bias[n + 2];
            v.w = acc[i][jq * 4 + 3] + bias[n + 3];
            if (MODE == 0) {
                int h = n >> 6, d = n & 63;
                *(float4*)(Cp + (((size_t)(bw * HH + h) * SSQ + s) * HD + d)) = v;
            } else if (MODE == 1) {
                const float* rr = resid
                    + ((size_t)((b * TT + tg) * LLE + l) << 10) + n;
                float4 r4 = *(const float4*)rr;
                v.x += r4.x; v.y += r4.y; v.z += r4.z; v.w += r4.w;
                size_t fr = (size_t)(b * TLTOK + tg * LLE + l);
                *(float4*)(Cp + (fr << 10) + n) = v;
            } else {
                v.x = gelu_f(v.x); v.y = gelu_f(v.y);
                v.z = gelu_f(v.z); v.w = gelu_f(v.w);
                *(float4*)(Cp + (size_t)m * DG + n) = v;
            }
        }
    }
}

// ---------------------------------------------------------------------------
// RMS norm over head dim (64), one warp per row. scale folds HD^-0.5 into q.
// ---------------------------------------------------------------------------
__global__ __launch_bounds__(256) void rms_k(int which, const float* __restrict__ w,
                                             float scale)
{
    float* X = which ? g_K : g_Q;
    int row  = blockIdx.x * 8 + (threadIdx.x >> 5);
    int lane = threadIdx.x & 31;
    float* p = X + (size_t)row * HD;
    float x0 = p[lane], x1 = p[lane + 32];
    float ss = x0 * x0 + x1 * x1;
    #pragma unroll
    for (int m = 16; m; m >>= 1) ss += __shfl_xor_sync(0xffffffffu, ss, m);
    float rs = rsqrtf(ss * (1.0f / 64.0f) + 1e-6f) * scale;
    p[lane]      = x0 * rs * w[lane];
    p[lane + 32] = x1 * rs * w[lane + 32];
}

// ---------------------------------------------------------------------------
// Windowed attention with online softmax.
// Block: one (window*head, 32 q-rows). 256 threads as 16(tx: 4 keys / 4 out-
// dims) x 16(ty: 2 q-rows). K/V share a union smem buffer; bias is a scalar
// per (q-temporal, key-tile) since key tiles align with L=64.
// ---------------------------------------------------------------------------
__global__ __launch_bounds__(256) void attn_k(const float* __restrict__ rpb,
                                              int dummy)
{
    __shared__ float Qst[64][33];   // [d][q]
    __shared__ float KVs[64][65];   // [key][d] (K then V, reused)
    __shared__ float Pst[64][33];   // [key][q]

    const int tid = threadIdx.x;
    const int tx = tid & 15, ty = tid >> 4;
    const int bh = blockIdx.x;           // bw*16 + h
    const int q0 = blockIdx.y * 32;
    const int h  = bh & 15;
    const int tq = blockIdx.y >> 1;      // temporal coord of these q rows
    const int bw = bh >> 4;

    const float* Qb = g_Q + (size_t)bh * SSQ * HD;
    const float* Kb = g_K + (size_t)bh * SSQ * HD;
    const float* Vb = g_V + (size_t)bh * SSQ * HD;

    {   // load Q tile transposed
        int qi = tid >> 3;
        int dg = (tid & 7) * 8;
        #pragma unroll
        for (int u = 0; u < 2; u++) {
            float4 q4 = *(const float4*)(Qb + (size_t)(q0 + qi) * HD + dg + u * 4);
            Qst[dg + u * 4 + 0][qi] = q4.x;
            Qst[dg + u * 4 + 1][qi] = q4.y;
            Qst[dg + u * 4 + 2][qi] = q4.z;
            Qst[dg + u * 4 + 3][qi] = q4.w;
        }
    }

    float m_i[2] = {-1e30f, -1e30f};
    float l_i[2] = {0.f, 0.f};
    float oa[2][4] = {{0, 0, 0, 0}, {0, 0, 0, 0}};

    const int kk = tid >> 2;           // key row for loads (0..63)
    const int kd = (tid & 3) * 16;     // d offset for loads

    for (int kt = 0; kt < 8; kt++) {
        const float bias_s = rpb[(tq - kt + 7) * HH + h];

        __syncthreads();               // prev-iter V readers done (also Q ready)
        #pragma unroll
        for (int u = 0; u < 4; u++) {  // K tile
            float4 t4 = *(const float4*)(Kb + (size_t)(kt * 64 + kk) * HD + kd + u * 4);
            KVs[kk][kd + u * 4 + 0] = t4.x;
            KVs[kk][kd + u * 4 + 1] = t4.y;
            KVs[kk][kd + u * 4 + 2] = t4.z;
            KVs[kk][kd + u * 4 + 3] = t4.w;
        }
        __syncthreads();

        float sc[2][4] = {{0, 0, 0, 0}, {0, 0, 0, 0}};
        #pragma unroll 8
        for (int d = 0; d < 64; d++) {
            float a0 = Qst[d][ty * 2 + 0];
            float a1 = Qst[d][ty * 2 + 1];
            float b0 = KVs[tx * 4 + 0][d];
            float b1 = KVs[tx * 4 + 1][d];
            float b2 = KVs[tx * 4 + 2][d];
            float b3 = KVs[tx * 4 + 3][d];
            sc[0][0] = fmaf(a0, b0, sc[0][0]); sc[0][1] = fmaf(a0, b1, sc[0][1]);
            sc[0][2] = fmaf(a0, b2, sc[0][2]); sc[0][3] = fmaf(a0, b3, sc[0][3]);
            sc[1][0] = fmaf(a1, b0, sc[1][0]); sc[1][1] = fmaf(a1, b1, sc[1][1]);
            sc[1][2] = fmaf(a1, b2, sc[1][2]); sc[1][3] = fmaf(a1, b3, sc[1][3]);
        }
        __syncthreads();               // done reading K

        #pragma unroll
        for (int u = 0; u < 4; u++) {  // V tile (overwrites K)
            float4 t4 = *(const float4*)(Vb + (size_t)(kt * 64 + kk) * HD + kd + u * 4);
            KVs[kk][kd + u * 4 + 0] = t4.x;
            KVs[kk][kd + u * 4 + 1] = t4.y;
            KVs[kk][kd + u * 4 + 2] = t4.z;
            KVs[kk][kd + u * 4 + 3] = t4.w;
        }

        // online softmax update (row groups = 16 lanes sharing ty)
        #pragma unroll
        for (int i = 0; i < 2; i++) {
            float mx = fmaxf(fmaxf(sc[i][0], sc[i][1]), fmaxf(sc[i][2], sc[i][3]));
            mx += bias_s;
            #pragma unroll
            for (int msk = 8; msk; msk >>= 1)
                mx = fmaxf(mx, __shfl_xor_sync(0xffffffffu, mx, msk));
            float mn = fmaxf(m_i[i], mx);
            float p0 = __expf(sc[i][0] + bias_s - mn);
            float p1 = __expf(sc[i][1] + bias_s - mn);
            float p2 = __expf(sc[i][2] + bias_s - mn);
            float p3 = __expf(sc[i][3] + bias_s - mn);
            float rs = p0 + p1 + p2 + p3;
            #pragma unroll
            for (int msk = 8; msk; msk >>= 1)
                rs += __shfl_xor_sync(0xffffffffu, rs, msk);
            float fac = __expf(m_i[i] - mn);
            l_i[i] = l_i[i] * fac + rs;
            oa[i][0] *= fac; oa[i][1] *= fac; oa[i][2] *= fac; oa[i][3] *= fac;
            m_i[i] = mn;
            Pst[tx * 4 + 0][ty * 2 + i] = p0;
            Pst[tx * 4 + 1][ty * 2 + i] = p1;
            Pst[tx * 4 + 2][ty * 2 + i] = p2;
            Pst[tx * 4 + 3][ty * 2 + i] = p3;
        }
        __syncthreads();               // V + P visible

        #pragma unroll 4
        for (int k = 0; k < 64; k++) {
            float a0 = Pst[k][ty * 2 + 0];
            float a1 = Pst[k][ty * 2 + 1];
            float v0 = KVs[k][tx * 4 + 0];
            float v1 = KVs[k][tx * 4 + 1];
            float v2 = KVs[k][tx * 4 + 2];
            float v3 = KVs[k][tx * 4 + 3];
            oa[0][0] = fmaf(a0, v0, oa[0][0]); oa[0][1] = fmaf(a0, v1, oa[0][1]);
            oa[0][2] = fmaf(a0, v2, oa[0][2]); oa[0][3] = fmaf(a0, v3, oa[0][3]);
            oa[1][0] = fmaf(a1, v0, oa[1][0]); oa[1][1] = fmaf(a1, v1, oa[1][1]);
            oa[1][2] = fmaf(a1, v2, oa[1][2]); oa[1][3] = fmaf(a1, v3, oa[1][3]);
        }
    }

    #pragma unroll
    for (int i = 0; i < 2; i++) {
        float inv = 1.0f / l_i[i];
        float4 w4 = {oa[i][0] * inv, oa[i][1] * inv, oa[i][2] * inv, oa[i][3] * inv};
        *(float4*)(g_O + (size_t)(bw * SSQ + q0 + ty * 2 + i) * DD + h * HD + tx * 4) = w4;
    }
}

// ---------------------------------------------------------------------------
// Gate logits + softmax + fused output. One block per token row.
// ---------------------------------------------------------------------------
__global__ __launch_bounds__(256) void gate_fuse_k(const float* __restrict__ Wg2,
                                                   const float* __restrict__ bg2,
                                                   float* __restrict__ out)
{
    const int row = blockIdx.x;
    const int tid = threadIdx.x;
    const float* g = g_G + (size_t)row * DG;
    float s0 = 0.f, s1 = 0.f, s2 = 0.f;
    for (int k = tid; k < DG; k += 256) {
        float x = g[k];
        s0 = fmaf(x, Wg2[k * 3 + 0], s0);
        s1 = fmaf(x, Wg2[k * 3 + 1], s1);
        s2 = fmaf(x, Wg2[k * 3 + 2], s2);
    }
    #pragma unroll
    for (int m = 16; m; m >>= 1) {
        s0 += __shfl_xor_sync(0xffffffffu, s0, m);
        s1 += __shfl_xor_sync(0xffffffffu, s1, m);
        s2 += __shfl_xor_sync(0xffffffffu, s2, m);
    }
    __shared__ float red[3][8];
    __shared__ float gl[3];
    int wid = tid >> 5, lane = tid & 31;
    if (lane == 0) { red[0][wid] = s0; red[1][wid] = s1; red[2][wid] = s2; }
    __syncthreads();
    if (tid < 3) {
        float s = bg2[tid];
        #pragma unroll
        for (int w = 0; w < 8; w++) s += red[tid][w];
        gl[tid] = s;
    }
    __syncthreads();
    float a0 = gl[0], a1 = gl[1], a2 = gl[2];
    float mx = fmaxf(a0, fmaxf(a1, a2));
    float e0 = __expf(a0 - mx), e1 = __expf(a1 - mx), e2 = __expf(a2 - mx);
    float inv = 1.0f / (e0 + e1 + e2);
    e0 *= inv; e1 *= inv; e2 *= inv;

    const float4* f0 = (const float4*)(g_feats + ((size_t)0 * BTLR + row) * DD);
    const float4* f1 = (const float4*)(g_feats + ((size_t)1 * BTLR + row) * DD);
    const float4* f2 = (const float4*)(g_feats + ((size_t)2 * BTLR + row) * DD);
    float4* o4 = (float4*)(out + (size_t)row * DD);
    float4 v0 = f0[tid], v1 = f1[tid], v2 = f2[tid];
    float4 r;
    r.x = e0 * v0.x + e1 * v1.x + e2 * v2.x;
    r.y = e0 * v0.y + e1 * v1.y + e2 * v2.y;
    r.z = e0 * v0.z + e1 * v1.z + e2 * v2.z;
    r.w = e0 * v0.w + e1 * v1.w + e2 * v2.w;
    o4[tid] = r;
}

// ---------------------------------------------------------------------------
// Launch
// ---------------------------------------------------------------------------
extern "C" void kernel_launch(void* const* d_in, const int* in_sizes, int n_in,
                              void* d_out, int out_size)
{
    const float* audio = (const float*)d_in[0];
    const float* video = (const float*)d_in[1];
    const float* image = (const float*)d_in[2];
    const float* Wq    = (const float*)d_in[3];
    const float* Wk    = (const float*)d_in[4];
    const float* Wv    = (const float*)d_in[5];
    const float* Wp    = (const float*)d_in[6];
    const float* bq    = (const float*)d_in[7];
    const float* bk    = (const float*)d_in[8];
    const float* bv    = (const float*)d_in[9];
    const float* bp    = (const float*)d_in[10];
    const float* qn    = (const float*)d_in[11];
    const float* kn    = (const float*)d_in[12];
    const float* rpb   = (const float*)d_in[13];
    const float* Wg1   = (const float*)d_in[14];
    const float* bg1   = (const float*)d_in[15];
    const float* Wg2   = (const float*)d_in[16];
    const float* bg2   = (const float*)d_in[17];
    float* out = (float*)d_out;

    const float* qs[3] = {audio, video, image};
    const float* ks[3] = {video, audio, video};

    dim3 blk(256);
    dim3 gP(8, 32);   // N=1024, M=4096

    for (int j = 0; j < 3; j++) {
        size_t wo = (size_t)j * DD * DD;
        gemm_k<0><<<gP, blk>>>(qs[j], Wq + wo, bq + j * DD, nullptr, 0, DD, DD);
        gemm_k<0><<<gP, blk>>>(ks[j], Wk + wo, bk + j * DD, nullptr, 1, DD, DD);
        gemm_k<0><<<gP, blk>>>(ks[j], Wv + wo, bv + j * DD, nullptr, 2, DD, DD);
        rms_k<<<8192, 256>>>(0, qn + j * HD, 0.125f);   // fold HD^-0.5 into q
        rms_k<<<8192, 256>>>(1, kn + j * HD, 1.0f);
        attn_k<<<dim3(128, 16), blk>>>(rpb + j * 15 * HH, 0);
        gemm_k<1><<<gP, blk>>>(nullptr, Wp + wo, bp + j * DD, qs[j], j, DD, DD);
    }
    gemm_k<2><<<dim3(16, 32), blk>>>(nullptr, Wg1, bg1, nullptr, 0, K3D, DG);
    gate_fuse_k<<<BTLR, 256>>>(Wg2, bg2, out);
}

// round 4
// speedup vs baseline: 1.3746x; 1.3746x over previous
#include <cuda_runtime.h>
#include <math.h>
#include <stdint.h>

#define BB 2
#define TT 32
#define LLE 64
#define DD 1024
#define HH 16
#define HD 64
#define NWIN 8
#define SSQ 512
#define AROWS 4096
#define TLTOK 2048
#define BTLR 4096
#define DG 2048
#define K3D 3072
#define FEATSZ ((size_t)BTLR * DD)
#define SROW 36
#define TILEF (128 * SROW)               // floats per tile buffer
#define SMEMB (4 * TILEF * 4)            // 73728 bytes

__device__ float g_Q[NWIN * HH * SSQ * HD];
__device__ float g_K[NWIN * HH * SSQ * HD];
__device__ float g_V[NWIN * HH * SSQ * HD];
__device__ float g_O[(size_t)AROWS * DD];
__device__ float g_feats[(size_t)3 * BTLR * DD];
__device__ float g_G[(size_t)BTLR * DG];
__device__ float g_Wt[(size_t)12 * DD * DD + (size_t)DG * K3D];

__device__ __forceinline__ float gelu_f(float x) {
    return 0.5f * x * (1.0f + erff(x * 0.70710678118654752440f));
}
__device__ __forceinline__ float to_tf32(float x) {
    uint32_t u; asm("cvt.rna.tf32.f32 %0, %1;" : "=r"(u) : "f"(x));
    return __uint_as_float(u);
}
__device__ __forceinline__ uint4 cvt4(float4 v) {
    uint4 u;
    asm("cvt.rna.tf32.f32 %0, %1;" : "=r"(u.x) : "f"(v.x));
    asm("cvt.rna.tf32.f32 %0, %1;" : "=r"(u.y) : "f"(v.y));
    asm("cvt.rna.tf32.f32 %0, %1;" : "=r"(u.z) : "f"(v.z));
    asm("cvt.rna.tf32.f32 %0, %1;" : "=r"(u.w) : "f"(v.w));
    return u;
}
__device__ __forceinline__ void mma8(float* d, const uint32_t* a, const uint32_t* b) {
    asm volatile("mma.sync.aligned.m16n8k8.row.col.f32.tf32.tf32.f32 "
        "{%0,%1,%2,%3}, {%4,%5,%6,%7}, {%8,%9}, {%0,%1,%2,%3};"
        : "+f"(d[0]), "+f"(d[1]), "+f"(d[2]), "+f"(d[3])
        : "r"(a[0]), "r"(a[1]), "r"(a[2]), "r"(a[3]), "r"(b[0]), "r"(b[1]));
}

// ---------------- weight transposes (tf32-rounded, [n][k]) ----------------
__global__ __launch_bounds__(256) void transW_k(
    const float* __restrict__ Wq, const float* __restrict__ Wk,
    const float* __restrict__ Wv, const float* __restrict__ Wp)
{
    __shared__ float tile[32][33];
    const int z = blockIdx.z;
    const float* W = (z < 3) ? Wq + (size_t)z * DD * DD
                   : (z < 6) ? Wk + (size_t)(z - 3) * DD * DD
                   : (z < 9) ? Wv + (size_t)(z - 6) * DD * DD
                             : Wp + (size_t)(z - 9) * DD * DD;
    float* Wt = g_Wt + (size_t)z * DD * DD;
    const int n0 = blockIdx.x << 5, k0 = blockIdx.y << 5;
    const int tx = threadIdx.x & 31, ty = threadIdx.x >> 5;
    #pragma unroll
    for (int j = 0; j < 32; j += 8)
        tile[ty + j][tx] = to_tf32(W[(size_t)(k0 + ty + j) * DD + n0 + tx]);
    __syncthreads();
    #pragma unroll
    for (int j = 0; j < 32; j += 8)
        Wt[(size_t)(n0 + ty + j) * DD + k0 + tx] = tile[tx][ty + j];
}
__global__ __launch_bounds__(256) void transG_k(const float* __restrict__ Wg1)
{
    __shared__ float tile[32][33];
    float* Wt = g_Wt + (size_t)12 * DD * DD;
    const int n0 = blockIdx.x << 5, k0 = blockIdx.y << 5;
    const int tx = threadIdx.x & 31, ty = threadIdx.x >> 5;
    #pragma unroll
    for (int j = 0; j < 32; j += 8)
        tile[ty + j][tx] = to_tf32(Wg1[(size_t)(k0 + ty + j) * DG + n0 + tx]);
    __syncthreads();
    #pragma unroll
    for (int j = 0; j < 32; j += 8)
        Wt[(size_t)(n0 + ty + j) * K3D + k0 + tx] = tile[tx][ty + j];
}

// ---------------------------------------------------------------------------
// tf32 mma.sync GEMM. Tile M=128 N=128, K-chunk=32, double-buffered smem.
// 8 warps as 4(m)x2(n); warp tile 32x64 via m16n8k8.
// MODE 0: QKV (roll-gathered A; +bias, fused RMS, scatter [NWIN*H][S][HD])
// MODE 1: out-proj (A=g_O; +bias +residual -> g_feats)
// MODE 2: gate L1 (A=concat feats; gelu -> g_G)
// ---------------------------------------------------------------------------
template<int MODE>
__global__ __launch_bounds__(256) void tgemm_k(
    const float* __restrict__ A0, size_t wt_off,
    const float* __restrict__ bias, const float* __restrict__ resid,
    const float* __restrict__ nw, float nscale, int which, int K)
{
    extern __shared__ float sm[];   // As0 As1 Bs0 Bs1, each 128*36 floats

    const int tid = threadIdx.x;
    const int wid = tid >> 5, lane = tid & 31;
    const int warpm = wid & 3, warpn = wid >> 2;
    const int g = lane >> 2, t = lane & 3;
    const int m0 = blockIdx.y << 7, n0 = blockIdx.x << 7;
    const int ra = tid >> 1, ka = (tid & 1) << 4;   // A/B stage: 2 thr/row, 16 floats

    size_t arow = 0;
    if (MODE == 0) {
        const int r = m0 + ra;
        const int bw = r >> 9, s = r & 511;
        const int b = bw >> 2, w = bw & 3;
        const int st = s >> 6, l = s & 63;
        const int tt = (w * 8 + st + 4) & 31;        // roll(-SH) gather
        arow = (size_t)((b * TT + tt) * LLE + l) << 10;
    } else {
        arow = (size_t)(m0 + ra) << 10;
    }
    const float* Bw = g_Wt + wt_off + (size_t)(n0 + ra) * K + ka;
    const float* Am = (MODE == 0) ? A0 : g_O;

    uint4 pa[4]; float4 pb[4];
#define LOADG(k0c) do {                                                           \
    if (MODE == 2) {                                                              \
        const int kg_ = (k0c) + ka;                                               \
        const float* bs_ = g_feats + (size_t)(kg_ >> 10) * FEATSZ                 \
                         + ((size_t)(m0 + ra) << 10) + (kg_ & 1023);              \
        _Pragma("unroll")                                                         \
        for (int i_ = 0; i_ < 4; i_++) pa[i_] = cvt4(*(const float4*)(bs_ + i_*4)); \
    } else {                                                                      \
        _Pragma("unroll")                                                         \
        for (int i_ = 0; i_ < 4; i_++)                                            \
            pa[i_] = cvt4(*(const float4*)(Am + arow + (k0c) + ka + i_*4));       \
    }                                                                             \
    _Pragma("unroll")                                                             \
    for (int i_ = 0; i_ < 4; i_++) pb[i_] = *(const float4*)(Bw + (k0c) + i_*4);  \
} while (0)
#define STOREG(bf_) do {                                                          \
    _Pragma("unroll")                                                             \
    for (int i_ = 0; i_ < 4; i_++)                                                \
        *(uint4*)&sm[(bf_)*TILEF + ra*SROW + ka + i_*4] = pa[i_];                 \
    _Pragma("unroll")                                                             \
    for (int i_ = 0; i_ < 4; i_++)                                                \
        *(float4*)&sm[2*TILEF + (bf_)*TILEF + ra*SROW + ka + i_*4] = pb[i_];      \
} while (0)

    float acc[2][8][4];
    #pragma unroll
    for (int i = 0; i < 2; i++)
        #pragma unroll
        for (int j = 0; j < 8; j++)
            #pragma unroll
            for (int q = 0; q < 4; q++) acc[i][j][q] = 0.f;

    const int NC = K >> 5;
    LOADG(0);
    STOREG(0);
    __syncthreads();

    for (int c = 0; c < NC; c++) {
        if (c + 1 < NC) LOADG((c + 1) << 5);
        const float* as = sm + (c & 1) * TILEF;
        const float* bs = sm + 2 * TILEF + (c & 1) * TILEF;
        #pragma unroll
        for (int ks = 0; ks < 4; ks++) {
            const int k0 = ks * 8;
            uint32_t af[2][4], bf[8][2];
            #pragma unroll
            for (int mi = 0; mi < 2; mi++) {
                const float* ar = as + (warpm * 32 + mi * 16 + g) * SROW + k0 + t;
                af[mi][0] = __float_as_uint(ar[0]);
                af[mi][1] = __float_as_uint(ar[8 * SROW]);
                af[mi][2] = __float_as_uint(ar[4]);
                af[mi][3] = __float_as_uint(ar[8 * SROW + 4]);
            }
            #pragma unroll
            for (int ni = 0; ni < 8; ni++) {
                const float* br = bs + (warpn * 64 + ni * 8 + g) * SROW + k0 + t;
                bf[ni][0] = __float_as_uint(br[0]);
                bf[ni][1] = __float_as_uint(br[4]);
            }
            #pragma unroll
            for (int mi = 0; mi < 2; mi++)
                #pragma unroll
                for (int ni = 0; ni < 8; ni++)
                    mma8(acc[mi][ni], af[mi], bf[ni]);
        }
        if (c + 1 < NC) STOREG((c + 1) & 1);
        __syncthreads();
    }

    // ---- epilogue: thread holds rows {base+g, base+g+8} x cols {ni*8+2t,+1} ----
    float2 bz[8], nz[8];
    #pragma unroll
    for (int ni = 0; ni < 8; ni++)
        bz[ni] = *(const float2*)(bias + n0 + warpn * 64 + ni * 8 + 2 * t);
    if (MODE == 0 && nw) {
        #pragma unroll
        for (int ni = 0; ni < 8; ni++)
            nz[ni] = *(const float2*)(nw + ni * 8 + 2 * t);
    }

    #pragma unroll
    for (int mi = 0; mi < 2; mi++)
    #pragma unroll
    for (int rh = 0; rh < 2; rh++) {
        const int m = m0 + warpm * 32 + mi * 16 + rh * 8 + g;
        float v[16];
        #pragma unroll
        for (int ni = 0; ni < 8; ni++) {
            v[2*ni]   = acc[mi][ni][2*rh]   + bz[ni].x;
            v[2*ni+1] = acc[mi][ni][2*rh+1] + bz[ni].y;
        }
        if (MODE == 0) {
            float* Cp = (which == 0) ? g_Q : (which == 1) ? g_K : g_V;
            const int bw = m >> 9, s = m & 511;
            const int h = (n0 + warpn * 64) >> 6;
            if (nw) {
                float ss = 0.f;
                #pragma unroll
                for (int j = 0; j < 16; j++) ss = fmaf(v[j], v[j], ss);
                ss += __shfl_xor_sync(0xffffffffu, ss, 1);
                ss += __shfl_xor_sync(0xffffffffu, ss, 2);
                const float rs = rsqrtf(ss * (1.f / 64.f) + 1e-6f) * nscale;
                #pragma unroll
                for (int ni = 0; ni < 8; ni++) {
                    v[2*ni]   *= rs * nz[ni].x;
                    v[2*ni+1] *= rs * nz[ni].y;
                }
            }
            float* dst = Cp + (((size_t)(bw * HH + h) * SSQ + s) << 6) + 2 * t;
            #pragma unroll
            for (int ni = 0; ni < 8; ni++)
                *(float2*)(dst + ni * 8) = make_float2(v[2*ni], v[2*ni+1]);
        } else if (MODE == 1) {
            const int bw = m >> 9, s = m & 511;
            const int b = bw >> 2, w = bw & 3;
            const int st = s >> 6, l = s & 63;
            const int tg = (w * 8 + st + 4) & 31;    // roll(+SH) scatter
            const float* rr = resid + ((size_t)((b * TT + tg) * LLE + l) << 10)
                            + n0 + warpn * 64 + 2 * t;
            float* fp = g_feats + (size_t)which * FEATSZ
                      + ((size_t)(b * TLTOK + tg * LLE + l) << 10)
                      + n0 + warpn * 64 + 2 * t;
            #pragma unroll
            for (int ni = 0; ni < 8; ni++) {
                float2 r2 = *(const float2*)(rr + ni * 8);
                *(float2*)(fp + ni * 8) = make_float2(v[2*ni] + r2.x, v[2*ni+1] + r2.y);
            }
        } else {
            float* gp = g_G + (size_t)m * DG + n0 + warpn * 64 + 2 * t;
            #pragma unroll
            for (int ni = 0; ni < 8; ni++)
                *(float2*)(gp + ni * 8) = make_float2(gelu_f(v[2*ni]), gelu_f(v[2*ni+1]));
        }
    }
}

// ---------------------------------------------------------------------------
// Windowed attention (fp32, online softmax) — unchanged passing version.
// ---------------------------------------------------------------------------
__global__ __launch_bounds__(256) void attn_k(const float* __restrict__ rpb, int)
{
    __shared__ float Qst[64][33];
    __shared__ float KVs[64][65];
    __shared__ float Pst[64][33];

    const int tid = threadIdx.x;
    const int tx = tid & 15, ty = tid >> 4;
    const int bh = blockIdx.x;
    const int q0 = blockIdx.y * 32;
    const int h = bh & 15;
    const int tq = blockIdx.y >> 1;
    const int bw = bh >> 4;

    const float* Qb = g_Q + (size_t)bh * SSQ * HD;
    const float* Kb = g_K + (size_t)bh * SSQ * HD;
    const float* Vb = g_V + (size_t)bh * SSQ * HD;

    {
        int qi = tid >> 3, dg = (tid & 7) * 8;
        #pragma unroll
        for (int u = 0; u < 2; u++) {
            float4 q4 = *(const float4*)(Qb + (size_t)(q0 + qi) * HD + dg + u * 4);
            Qst[dg + u * 4 + 0][qi] = q4.x; Qst[dg + u * 4 + 1][qi] = q4.y;
            Qst[dg + u * 4 + 2][qi] = q4.z; Qst[dg + u * 4 + 3][qi] = q4.w;
        }
    }
    float m_i[2] = {-1e30f, -1e30f}, l_i[2] = {0.f, 0.f};
    float oa[2][4] = {{0,0,0,0},{0,0,0,0}};
    const int kk = tid >> 2, kd = (tid & 3) * 16;

    for (int kt = 0; kt < 8; kt++) {
        const float bias_s = rpb[(tq - kt + 7) * HH + h];
        __syncthreads();
        #pragma unroll
        for (int u = 0; u < 4; u++) {
            float4 t4 = *(const float4*)(Kb + (size_t)(kt * 64 + kk) * HD + kd + u * 4);
            KVs[kk][kd + u*4+0] = t4.x; KVs[kk][kd + u*4+1] = t4.y;
            KVs[kk][kd + u*4+2] = t4.z; KVs[kk][kd + u*4+3] = t4.w;
        }
        __syncthreads();
        float sc[2][4] = {{0,0,0,0},{0,0,0,0}};
        #pragma unroll 8
        for (int d = 0; d < 64; d++) {
            float a0 = Qst[d][ty*2+0], a1 = Qst[d][ty*2+1];
            float b0 = KVs[tx*4+0][d], b1 = KVs[tx*4+1][d];
            float b2 = KVs[tx*4+2][d], b3 = KVs[tx*4+3][d];
            sc[0][0]=fmaf(a0,b0,sc[0][0]); sc[0][1]=fmaf(a0,b1,sc[0][1]);
            sc[0][2]=fmaf(a0,b2,sc[0][2]); sc[0][3]=fmaf(a0,b3,sc[0][3]);
            sc[1][0]=fmaf(a1,b0,sc[1][0]); sc[1][1]=fmaf(a1,b1,sc[1][1]);
            sc[1][2]=fmaf(a1,b2,sc[1][2]); sc[1][3]=fmaf(a1,b3,sc[1][3]);
        }
        __syncthreads();
        #pragma unroll
        for (int u = 0; u < 4; u++) {
            float4 t4 = *(const float4*)(Vb + (size_t)(kt * 64 + kk) * HD + kd + u * 4);
            KVs[kk][kd + u*4+0] = t4.x; KVs[kk][kd + u*4+1] = t4.y;
            KVs[kk][kd + u*4+2] = t4.z; KVs[kk][kd + u*4+3] = t4.w;
        }
        #pragma unroll
        for (int i = 0; i < 2; i++) {
            float mx = fmaxf(fmaxf(sc[i][0], sc[i][1]), fmaxf(sc[i][2], sc[i][3]));
            mx += bias_s;
            #pragma unroll
            for (int msk = 8; msk; msk >>= 1)
                mx = fmaxf(mx, __shfl_xor_sync(0xffffffffu, mx, msk));
            float mn = fmaxf(m_i[i], mx);
            float p0 = __expf(sc[i][0] + bias_s - mn);
            float p1 = __expf(sc[i][1] + bias_s - mn);
            float p2 = __expf(sc[i][2] + bias_s - mn);
            float p3 = __expf(sc[i][3] + bias_s - mn);
            float rs = p0 + p1 + p2 + p3;
            #pragma unroll
            for (int msk = 8; msk; msk >>= 1)
                rs += __shfl_xor_sync(0xffffffffu, rs, msk);
            float fac = __expf(m_i[i] - mn);
            l_i[i] = l_i[i] * fac + rs;
            oa[i][0]*=fac; oa[i][1]*=fac; oa[i][2]*=fac; oa[i][3]*=fac;
            m_i[i] = mn;
            Pst[tx*4+0][ty*2+i]=p0; Pst[tx*4+1][ty*2+i]=p1;
            Pst[tx*4+2][ty*2+i]=p2; Pst[tx*4+3][ty*2+i]=p3;
        }
        __syncthreads();
        #pragma unroll 4
        for (int k = 0; k < 64; k++) {
            float a0 = Pst[k][ty*2+0], a1 = Pst[k][ty*2+1];
            float v0 = KVs[k][tx*4+0], v1 = KVs[k][tx*4+1];
            float v2 = KVs[k][tx*4+2], v3 = KVs[k][tx*4+3];
            oa[0][0]=fmaf(a0,v0,oa[0][0]); oa[0][1]=fmaf(a0,v1,oa[0][1]);
            oa[0][2]=fmaf(a0,v2,oa[0][2]); oa[0][3]=fmaf(a0,v3,oa[0][3]);
            oa[1][0]=fmaf(a1,v0,oa[1][0]); oa[1][1]=fmaf(a1,v1,oa[1][1]);
            oa[1][2]=fmaf(a1,v2,oa[1][2]); oa[1][3]=fmaf(a1,v3,oa[1][3]);
        }
    }
    #pragma unroll
    for (int i = 0; i < 2; i++) {
        float inv = 1.0f / l_i[i];
        float4 w4 = {oa[i][0]*inv, oa[i][1]*inv, oa[i][2]*inv, oa[i][3]*inv};
        *(float4*)(g_O + (size_t)(bw * SSQ + q0 + ty * 2 + i) * DD + h * HD + tx * 4) = w4;
    }
}

// ---------------------------------------------------------------------------
// Gate logits + softmax + fuse.
// ---------------------------------------------------------------------------
__global__ __launch_bounds__(256) void gate_fuse_k(const float* __restrict__ Wg2,
                                                   const float* __restrict__ bg2,
                                                   float* __restrict__ out)
{
    const int row = blockIdx.x, tid = threadIdx.x;
    const float* g = g_G + (size_t)row * DG;
    float s0 = 0.f, s1 = 0.f, s2 = 0.f;
    for (int k = tid; k < DG; k += 256) {
        float x = g[k];
        s0 = fmaf(x, Wg2[k*3+0], s0);
        s1 = fmaf(x, Wg2[k*3+1], s1);
        s2 = fmaf(x, Wg2[k*3+2], s2);
    }
    #pragma unroll
    for (int m = 16; m; m >>= 1) {
        s0 += __shfl_xor_sync(0xffffffffu, s0, m);
        s1 += __shfl_xor_sync(0xffffffffu, s1, m);
        s2 += __shfl_xor_sync(0xffffffffu, s2, m);
    }
    __shared__ float red[3][8];
    __shared__ float gl[3];
    int wid = tid >> 5, lane = tid & 31;
    if (lane == 0) { red[0][wid]=s0; red[1][wid]=s1; red[2][wid]=s2; }
    __syncthreads();
    if (tid < 3) {
        float s = bg2[tid];
        #pragma unroll
        for (int w = 0; w < 8; w++) s += red[tid][w];
        gl[tid] = s;
    }
    __syncthreads();
    float a0 = gl[0], a1 = gl[1], a2 = gl[2];
    float mx = fmaxf(a0, fmaxf(a1, a2));
    float e0 = __expf(a0-mx), e1 = __expf(a1-mx), e2 = __expf(a2-mx);
    float inv = 1.0f / (e0 + e1 + e2);
    e0 *= inv; e1 *= inv; e2 *= inv;
    const float4* f0 = (const float4*)(g_feats + (size_t)0*FEATSZ + (size_t)row*DD);
    const float4* f1 = (const float4*)(g_feats + (size_t)1*FEATSZ + (size_t)row*DD);
    const float4* f2 = (const float4*)(g_feats + (size_t)2*FEATSZ + (size_t)row*DD);
    float4* o4 = (float4*)(out + (size_t)row * DD);
    float4 v0 = f0[tid], v1 = f1[tid], v2 = f2[tid];
    o4[tid] = make_float4(e0*v0.x + e1*v1.x + e2*v2.x,
                          e0*v0.y + e1*v1.y + e2*v2.y,
                          e0*v0.z + e1*v1.z + e2*v2.z,
                          e0*v0.w + e1*v1.w + e2*v2.w);
}

// ---------------------------------------------------------------------------
// Launch
// ---------------------------------------------------------------------------
extern "C" void kernel_launch(void* const* d_in, const int* in_sizes, int n_in,
                              void* d_out, int out_size)
{
    const float* audio = (const float*)d_in[0];
    const float* video = (const float*)d_in[1];
    const float* image = (const float*)d_in[2];
    const float* Wq = (const float*)d_in[3];
    const float* Wk = (const float*)d_in[4];
    const float* Wv = (const float*)d_in[5];
    const float* Wp = (const float*)d_in[6];
    const float* bq = (const float*)d_in[7];
    const float* bk = (const float*)d_in[8];
    const float* bv = (const float*)d_in[9];
    const float* bp = (const float*)d_in[10];
    const float* qn = (const float*)d_in[11];
    const float* kn = (const float*)d_in[12];
    const float* rpb = (const float*)d_in[13];
    const float* Wg1 = (const float*)d_in[14];
    const float* bg1 = (const float*)d_in[15];
    const float* Wg2 = (const float*)d_in[16];
    const float* bg2 = (const float*)d_in[17];
    float* out = (float*)d_out;

    cudaFuncSetAttribute(tgemm_k<0>, cudaFuncAttributeMaxDynamicSharedMemorySize, SMEMB);
    cudaFuncSetAttribute(tgemm_k<1>, cudaFuncAttributeMaxDynamicSharedMemorySize, SMEMB);
    cudaFuncSetAttribute(tgemm_k<2>, cudaFuncAttributeMaxDynamicSharedMemorySize, SMEMB);

    const float* qs[3] = {audio, video, image};
    const float* ks[3] = {video, audio, video};
    dim3 blk(256);
    dim3 gP(8, 32);

    transW_k<<<dim3(32, 32, 12), blk>>>(Wq, Wk, Wv, Wp);
    transG_k<<<dim3(64, 96), blk>>>(Wg1);

    for (int j = 0; j < 3; j++) {
        size_t oq = (size_t)j * DD * DD;
        size_t ok = (size_t)(3 + j) * DD * DD;
        size_t ov = (size_t)(6 + j) * DD * DD;
        size_t op = (size_t)(9 + j) * DD * DD;
        tgemm_k<0><<<gP, blk, SMEMB>>>(qs[j], oq, bq + j*DD, nullptr, qn + j*HD, 0.125f, 0, DD);
        tgemm_k<0><<<gP, blk, SMEMB>>>(ks[j], ok, bk + j*DD, nullptr, kn + j*HD, 1.0f, 1, DD);
        tgemm_k<0><<<gP, blk, SMEMB>>>(ks[j], ov, bv + j*DD, nullptr, nullptr, 0.f, 2, DD);
        attn_k<<<dim3(128, 16), blk>>>(rpb + j * 15 * HH, 0);
        tgemm_k<1><<<gP, blk, SMEMB>>>(nullptr, op, bp + j*DD, qs[j], nullptr, 0.f, j, DD);
    }
    tgemm_k<2><<<dim3(16, 32), blk, SMEMB>>>(nullptr, (size_t)12 * DD * DD, bg1,
                                             nullptr, nullptr, 0.f, 0, K3D);
    gate_fuse_k<<<BTLR, 256>>>(Wg2, bg2, out);
}

// round 5
// speedup vs baseline: 2.6972x; 1.9622x over previous
#include <cuda_runtime.h>
#include <math.h>
#include <stdint.h>

#define BB 2
#define TT 32
#define LLE 64
#define DD 1024
#define HH 16
#define HD 64
#define NWIN 8
#define SSQ 512
#define AROWS 4096
#define TLTOK 2048
#define BTLR 4096
#define DG 2048
#define K3D 3072
#define FEATSZ ((size_t)BTLR * DD)
#define SROW 20
#define TILEF (128 * SROW)
#define SMEMB (4 * TILEF * 4)            // 40960 B -> 2 CTAs/SM
#define ASMEM ((128 * 68 + 64 * 68 + 64 * 68) * 4)   // 69632 B

__device__ float g_Q[NWIN * HH * SSQ * HD];
__device__ float g_K[NWIN * HH * SSQ * HD];
__device__ float g_V[NWIN * HH * SSQ * HD];
__device__ float g_O[(size_t)AROWS * DD];
__device__ float g_feats[(size_t)3 * BTLR * DD];
__device__ float g_G[(size_t)BTLR * DG];
__device__ float g_Wt[(size_t)12 * DD * DD + (size_t)DG * K3D];

__device__ __forceinline__ float gelu_f(float x) {
    return 0.5f * x * (1.0f + erff(x * 0.70710678118654752440f));
}
__device__ __forceinline__ float to_tf32(float x) {
    uint32_t u; asm("cvt.rna.tf32.f32 %0, %1;" : "=r"(u) : "f"(x));
    return __uint_as_float(u);
}
__device__ __forceinline__ uint4 cvt4(float4 v) {
    uint4 u;
    asm("cvt.rna.tf32.f32 %0, %1;" : "=r"(u.x) : "f"(v.x));
    asm("cvt.rna.tf32.f32 %0, %1;" : "=r"(u.y) : "f"(v.y));
    asm("cvt.rna.tf32.f32 %0, %1;" : "=r"(u.z) : "f"(v.z));
    asm("cvt.rna.tf32.f32 %0, %1;" : "=r"(u.w) : "f"(v.w));
    return u;
}
__device__ __forceinline__ uint32_t cvt1(float x) {
    uint32_t u; asm("cvt.rna.tf32.f32 %0, %1;" : "=r"(u) : "f"(x));
    return u;
}
__device__ __forceinline__ void mma8(float* d, const uint32_t* a, const uint32_t* b) {
    asm volatile("mma.sync.aligned.m16n8k8.row.col.f32.tf32.tf32.f32 "
        "{%0,%1,%2,%3}, {%4,%5,%6,%7}, {%8,%9}, {%0,%1,%2,%3};"
        : "+f"(d[0]), "+f"(d[1]), "+f"(d[2]), "+f"(d[3])
        : "r"(a[0]), "r"(a[1]), "r"(a[2]), "r"(a[3]), "r"(b[0]), "r"(b[1]));
}

// ---------------- weight transposes (tf32-rounded, [n][k]) ----------------
__global__ __launch_bounds__(256) void transW_k(
    const float* __restrict__ Wq, const float* __restrict__ Wk,
    const float* __restrict__ Wv, const float* __restrict__ Wp)
{
    __shared__ float tile[32][33];
    const int z = blockIdx.z;
    const float* W = (z < 3) ? Wq + (size_t)z * DD * DD
                   : (z < 6) ? Wk + (size_t)(z - 3) * DD * DD
                   : (z < 9) ? Wv + (size_t)(z - 6) * DD * DD
                             : Wp + (size_t)(z - 9) * DD * DD;
    float* Wt = g_Wt + (size_t)z * DD * DD;
    const int n0 = blockIdx.x << 5, k0 = blockIdx.y << 5;
    const int tx = threadIdx.x & 31, ty = threadIdx.x >> 5;
    #pragma unroll
    for (int j = 0; j < 32; j += 8)
        tile[ty + j][tx] = to_tf32(W[(size_t)(k0 + ty + j) * DD + n0 + tx]);
    __syncthreads();
    #pragma unroll
    for (int j = 0; j < 32; j += 8)
        Wt[(size_t)(n0 + ty + j) * DD + k0 + tx] = tile[tx][ty + j];
}
__global__ __launch_bounds__(256) void transG_k(const float* __restrict__ Wg1)
{
    __shared__ float tile[32][33];
    float* Wt = g_Wt + (size_t)12 * DD * DD;
    const int n0 = blockIdx.x << 5, k0 = blockIdx.y << 5;
    const int tx = threadIdx.x & 31, ty = threadIdx.x >> 5;
    #pragma unroll
    for (int j = 0; j < 32; j += 8)
        tile[ty + j][tx] = to_tf32(Wg1[(size_t)(k0 + ty + j) * DG + n0 + tx]);
    __syncthreads();
    #pragma unroll
    for (int j = 0; j < 32; j += 8)
        Wt[(size_t)(n0 + ty + j) * K3D + k0 + tx] = tile[tx][ty + j];
}

// ---------------------------------------------------------------------------
// tf32 mma.sync GEMM. Tile M=128 N=128, K-chunk=16, double-buffered, 2 CTA/SM.
// ---------------------------------------------------------------------------
template<int MODE>
__global__ __launch_bounds__(256, 2) void tgemm_k(
    const float* __restrict__ A0, size_t wt_off,
    const float* __restrict__ bias, const float* __restrict__ resid,
    const float* __restrict__ nw, float nscale, int which, int K)
{
    extern __shared__ float sm[];   // As0 As1 Bs0 Bs1, each 128*20 floats

    const int tid = threadIdx.x;
    const int wid = tid >> 5, lane = tid & 31;
    const int warpm = wid & 3, warpn = wid >> 2;
    const int g = lane >> 2, t = lane & 3;
    const int m0 = blockIdx.y << 7, n0 = blockIdx.x << 7;
    const int ra = tid >> 1, ka = (tid & 1) << 3;   // 2 thr/row, 8 floats each

    size_t arow = 0;
    if (MODE == 0) {
        const int r = m0 + ra;
        const int bw = r >> 9, s = r & 511;
        const int b = bw >> 2, w = bw & 3;
        const int st = s >> 6, l = s & 63;
        const int tt = (w * 8 + st + 4) & 31;        // roll(-SH) gather
        arow = (size_t)((b * TT + tt) * LLE + l) << 10;
    } else {
        arow = (size_t)(m0 + ra) << 10;
    }
    const float* Bw = g_Wt + wt_off + (size_t)(n0 + ra) * K + ka;
    const float* Am = (MODE == 0) ? A0 : g_O;

    uint4 pa[2]; float4 pb[2];
#define LOADG(k0c) do {                                                           \
    if (MODE == 2) {                                                              \
        const int kg_ = (k0c) + ka;                                               \
        const float* bs_ = g_feats + (size_t)(kg_ >> 10) * FEATSZ                 \
                         + ((size_t)(m0 + ra) << 10) + (kg_ & 1023);              \
        pa[0] = cvt4(*(const float4*)(bs_));                                      \
        pa[1] = cvt4(*(const float4*)(bs_ + 4));                                  \
    } else {                                                                      \
        pa[0] = cvt4(*(const float4*)(Am + arow + (k0c) + ka));                   \
        pa[1] = cvt4(*(const float4*)(Am + arow + (k0c) + ka + 4));               \
    }                                                                             \
    pb[0] = *(const float4*)(Bw + (k0c));                                         \
    pb[1] = *(const float4*)(Bw + (k0c) + 4);                                     \
} while (0)
#define STOREG(bf_) do {                                                          \
    *(uint4*)&sm[(bf_)*TILEF + ra*SROW + ka]     = pa[0];                         \
    *(uint4*)&sm[(bf_)*TILEF + ra*SROW + ka + 4] = pa[1];                         \
    *(float4*)&sm[2*TILEF + (bf_)*TILEF + ra*SROW + ka]     = pb[0];              \
    *(float4*)&sm[2*TILEF + (bf_)*TILEF + ra*SROW + ka + 4] = pb[1];              \
} while (0)

    float acc[2][8][4];
    #pragma unroll
    for (int i = 0; i < 2; i++)
        #pragma unroll
        for (int j = 0; j < 8; j++)
            #pragma unroll
            for (int q = 0; q < 4; q++) acc[i][j][q] = 0.f;

    const int NC = K >> 4;
    LOADG(0);
    STOREG(0);
    __syncthreads();

    for (int c = 0; c < NC; c++) {
        if (c + 1 < NC) LOADG((c + 1) << 4);
        const float* as = sm + (c & 1) * TILEF;
        const float* bs = sm + 2 * TILEF + (c & 1) * TILEF;
        #pragma unroll
        for (int ks = 0; ks < 2; ks++) {
            const int k0 = ks * 8;
            uint32_t af[2][4], bf[8][2];
            #pragma unroll
            for (int mi = 0; mi < 2; mi++) {
                const float* ar = as + (warpm * 32 + mi * 16 + g) * SROW + k0 + t;
                af[mi][0] = __float_as_uint(ar[0]);
                af[mi][1] = __float_as_uint(ar[8 * SROW]);
                af[mi][2] = __float_as_uint(ar[4]);
                af[mi][3] = __float_as_uint(ar[8 * SROW + 4]);
            }
            #pragma unroll
            for (int ni = 0; ni < 8; ni++) {
                const float* br = bs + (warpn * 64 + ni * 8 + g) * SROW + k0 + t;
                bf[ni][0] = __float_as_uint(br[0]);
                bf[ni][1] = __float_as_uint(br[4]);
            }
            #pragma unroll
            for (int mi = 0; mi < 2; mi++)
                #pragma unroll
                for (int ni = 0; ni < 8; ni++)
                    mma8(acc[mi][ni], af[mi], bf[ni]);
        }
        if (c + 1 < NC) STOREG((c + 1) & 1);
        __syncthreads();
    }

    // ---- epilogue ----
    float2 bz[8], nz[8];
    #pragma unroll
    for (int ni = 0; ni < 8; ni++)
        bz[ni] = *(const float2*)(bias + n0 + warpn * 64 + ni * 8 + 2 * t);
    if (MODE == 0 && nw) {
        #pragma unroll
        for (int ni = 0; ni < 8; ni++)
            nz[ni] = *(const float2*)(nw + ni * 8 + 2 * t);
    }

    #pragma unroll
    for (int mi = 0; mi < 2; mi++)
    #pragma unroll
    for (int rh = 0; rh < 2; rh++) {
        const int m = m0 + warpm * 32 + mi * 16 + rh * 8 + g;
        float v[16];
        #pragma unroll
        for (int ni = 0; ni < 8; ni++) {
            v[2*ni]   = acc[mi][ni][2*rh]   + bz[ni].x;
            v[2*ni+1] = acc[mi][ni][2*rh+1] + bz[ni].y;
        }
        if (MODE == 0) {
            float* Cp = (which == 0) ? g_Q : (which == 1) ? g_K : g_V;
            const int bw = m >> 9, s = m & 511;
            const int h = (n0 + warpn * 64) >> 6;
            if (nw) {
                float ss = 0.f;
                #pragma unroll
                for (int j = 0; j < 16; j++) ss = fmaf(v[j], v[j], ss);
                ss += __shfl_xor_sync(0xffffffffu, ss, 1);
                ss += __shfl_xor_sync(0xffffffffu, ss, 2);
                const float rs = rsqrtf(ss * (1.f / 64.f) + 1e-6f) * nscale;
                #pragma unroll
                for (int ni = 0; ni < 8; ni++) {
                    v[2*ni]   *= rs * nz[ni].x;
                    v[2*ni+1] *= rs * nz[ni].y;
                }
            }
            float* dst = Cp + (((size_t)(bw * HH + h) * SSQ + s) << 6) + 2 * t;
            #pragma unroll
            for (int ni = 0; ni < 8; ni++)
                *(float2*)(dst + ni * 8) = make_float2(v[2*ni], v[2*ni+1]);
        } else if (MODE == 1) {
            const int bw = m >> 9, s = m & 511;
            const int b = bw >> 2, w = bw & 3;
            const int st = s >> 6, l = s & 63;
            const int tg = (w * 8 + st + 4) & 31;    // roll(+SH) scatter
            const float* rr = resid + ((size_t)((b * TT + tg) * LLE + l) << 10)
                            + n0 + warpn * 64 + 2 * t;
            float* fp = g_feats + (size_t)which * FEATSZ
                      + ((size_t)(b * TLTOK + tg * LLE + l) << 10)
                      + n0 + warpn * 64 + 2 * t;
            #pragma unroll
            for (int ni = 0; ni < 8; ni++) {
                float2 r2 = *(const float2*)(rr + ni * 8);
                *(float2*)(fp + ni * 8) = make_float2(v[2*ni] + r2.x, v[2*ni+1] + r2.y);
            }
        } else {
            float* gp = g_G + (size_t)m * DG + n0 + warpn * 64 + 2 * t;
            #pragma unroll
            for (int ni = 0; ni < 8; ni++)
                *(float2*)(gp + ni * 8) = make_float2(gelu_f(v[2*ni]), gelu_f(v[2*ni+1]));
        }
    }
}

// ---------------------------------------------------------------------------
// Flash-style windowed attention on tensor cores (tf32 mma, fp32 softmax).
// Block = (bh, 128-q tile). 8 warps, each owns 16 q-rows.
// Smem: QP[128][68] (Q staging, then reused for P), Kt[64][68], Vt[64][68](=V^T).
// ---------------------------------------------------------------------------
__global__ __launch_bounds__(256) void attn_mma_k(const float* __restrict__ rpb)
{
    extern __shared__ float sma[];
    float* QP = sma;                  // 128*68
    float* Kt = sma + 128 * 68;       // 64*68
    float* Vt = Kt + 64 * 68;         // 64*68

    const int tid = threadIdx.x;
    const int wid = tid >> 5, lane = tid & 31;
    const int g = lane >> 2, t = lane & 3;
    const int bh = blockIdx.x, qt = blockIdx.y;
    const int h = bh & 15, bw = bh >> 4;
    const int q0 = qt << 7;
    const int tq = (qt << 1) + (wid >> 2);
    const int mrow = wid << 4;

    // stage Q (tf32-rounded)
    {
        const int r = tid >> 1, c0 = (tid & 1) << 5;
        const float* qs = g_Q + ((size_t)bh * SSQ + q0 + r) * HD + c0;
        #pragma unroll
        for (int u = 0; u < 8; u++)
            *(uint4*)&QP[r * 68 + c0 + u * 4] = cvt4(*(const float4*)(qs + u * 4));
    }
    __syncthreads();

    // persistent Q fragments
    uint32_t af[8][4];
    {
        const float* ab = QP + (mrow + g) * 68 + t;
        #pragma unroll
        for (int ks = 0; ks < 8; ks++) {
            af[ks][0] = __float_as_uint(ab[ks * 8]);
            af[ks][1] = __float_as_uint(ab[8 * 68 + ks * 8]);
            af[ks][2] = __float_as_uint(ab[ks * 8 + 4]);
            af[ks][3] = __float_as_uint(ab[8 * 68 + ks * 8 + 4]);
        }
    }
    __syncthreads();   // all Q frags in regs before QP is reused for P

    float oc[8][4];
    #pragma unroll
    for (int i = 0; i < 8; i++)
        #pragma unroll
        for (int q = 0; q < 4; q++) oc[i][q] = 0.f;
    float m_i[2] = {-1e30f, -1e30f}, l_i[2] = {0.f, 0.f};

    const int kr = tid >> 2, kc = (tid & 3) << 4;
    const int vk = tid & 63, vd = (tid >> 6) << 4;

    for (int kt = 0; kt < 8; kt++) {
        const float bias_s = rpb[(tq - kt + 7) * HH + h];
        // stage K [key][d] and V transposed [d][key]
        {
            const float* ksrc = g_K + ((size_t)bh * SSQ + (kt << 6) + kr) * HD + kc;
            #pragma unroll
            for (int u = 0; u < 4; u++)
                *(uint4*)&Kt[kr * 68 + kc + u * 4] = cvt4(*(const float4*)(ksrc + u * 4));
            const float* vsrc = g_V + ((size_t)bh * SSQ + (kt << 6) + vk) * HD + vd;
            #pragma unroll
            for (int u = 0; u < 4; u++) {
                uint4 vv = cvt4(*(const float4*)(vsrc + u * 4));
                Vt[(vd + u * 4 + 0) * 68 + vk] = __uint_as_float(vv.x);
                Vt[(vd + u * 4 + 1) * 68 + vk] = __uint_as_float(vv.y);
                Vt[(vd + u * 4 + 2) * 68 + vk] = __uint_as_float(vv.z);
                Vt[(vd + u * 4 + 3) * 68 + vk] = __uint_as_float(vv.w);
            }
        }
        __syncthreads();

        // S = Q K^T
        float sc[8][4];
        #pragma unroll
        for (int i = 0; i < 8; i++)
            #pragma unroll
            for (int q = 0; q < 4; q++) sc[i][q] = 0.f;
        #pragma unroll
        for (int ks = 0; ks < 8; ks++) {
            #pragma unroll
            for (int ni = 0; ni < 8; ni++) {
                const float* br = Kt + (ni * 8 + g) * 68 + ks * 8 + t;
                uint32_t bf[2] = { __float_as_uint(br[0]), __float_as_uint(br[4]) };
                mma8(sc[ni], af[ks], bf);
            }
        }

        // online softmax per row-half; P -> QP (tf32)
        #pragma unroll
        for (int hr = 0; hr < 2; hr++) {
            float mx = -1e30f;
            #pragma unroll
            for (int ni = 0; ni < 8; ni++)
                mx = fmaxf(mx, fmaxf(sc[ni][2*hr], sc[ni][2*hr+1]));
            mx += bias_s;
            mx = fmaxf(mx, __shfl_xor_sync(0xffffffffu, mx, 1));
            mx = fmaxf(mx, __shfl_xor_sync(0xffffffffu, mx, 2));
            const float mn = fmaxf(m_i[hr], mx);
            const float fac = __expf(m_i[hr] - mn);
            m_i[hr] = mn;
            float sum = 0.f;
            float* prow = QP + (mrow + hr * 8 + g) * 68 + 2 * t;
            #pragma unroll
            for (int ni = 0; ni < 8; ni++) {
                float p0 = __expf(sc[ni][2*hr]   + bias_s - mn);
                float p1 = __expf(sc[ni][2*hr+1] + bias_s - mn);
                sum += p0 + p1;
                uint2 pk = { cvt1(p0), cvt1(p1) };
                *(uint2*)(prow + ni * 8) = pk;
            }
            sum += __shfl_xor_sync(0xffffffffu, sum, 1);
            sum += __shfl_xor_sync(0xffffffffu, sum, 2);
            l_i[hr] = l_i[hr] * fac + sum;
            #pragma unroll
            for (int ni = 0; ni < 8; ni++) {
                oc[ni][2*hr]   *= fac;
                oc[ni][2*hr+1] *= fac;
            }
        }
        __syncwarp();   // P is warp-private (warp writes+reads only its 16 rows)

        // O += P V
        #pragma unroll
        for (int ks = 0; ks < 8; ks++) {
            const float* pb = QP + (mrow + g) * 68 + ks * 8 + t;
            uint32_t pf[4] = { __float_as_uint(pb[0]), __float_as_uint(pb[8 * 68]),
                               __float_as_uint(pb[4]), __float_as_uint(pb[8 * 68 + 4]) };
            #pragma unroll
            for (int ni = 0; ni < 8; ni++) {
                const float* vr = Vt + (ni * 8 + g) * 68 + ks * 8 + t;
                uint32_t vf[2] = { __float_as_uint(vr[0]), __float_as_uint(vr[4]) };
                mma8(oc[ni], pf, vf);
            }
        }
        __syncthreads();   // done with Kt/Vt before next stage overwrites
    }

    const float inv0 = 1.0f / l_i[0], inv1 = 1.0f / l_i[1];
    #pragma unroll
    for (int hr = 0; hr < 2; hr++) {
        const float inv = hr ? inv1 : inv0;
        const int row = q0 + mrow + hr * 8 + g;
        float* dst = g_O + ((size_t)(bw * SSQ + row)) * DD + h * HD + 2 * t;
        #pragma unroll
        for (int ni = 0; ni < 8; ni++)
            *(float2*)(dst + ni * 8) = make_float2(oc[ni][2*hr] * inv,
                                                   oc[ni][2*hr+1] * inv);
    }
}

// ---------------------------------------------------------------------------
// Gate logits + softmax + fuse.
// ---------------------------------------------------------------------------
__global__ __launch_bounds__(256) void gate_fuse_k(const float* __restrict__ Wg2,
                                                   const float* __restrict__ bg2,
                                                   float* __restrict__ out)
{
    const int row = blockIdx.x, tid = threadIdx.x;
    const float* g = g_G + (size_t)row * DG;
    float s0 = 0.f, s1 = 0.f, s2 = 0.f;
    for (int k = tid; k < DG; k += 256) {
        float x = g[k];
        s0 = fmaf(x, Wg2[k*3+0], s0);
        s1 = fmaf(x, Wg2[k*3+1], s1);
        s2 = fmaf(x, Wg2[k*3+2], s2);
    }
    #pragma unroll
    for (int m = 16; m; m >>= 1) {
        s0 += __shfl_xor_sync(0xffffffffu, s0, m);
        s1 += __shfl_xor_sync(0xffffffffu, s1, m);
        s2 += __shfl_xor_sync(0xffffffffu, s2, m);
    }
    __shared__ float red[3][8];
    __shared__ float gl[3];
    int wid = tid >> 5, lane = tid & 31;
    if (lane == 0) { red[0][wid]=s0; red[1][wid]=s1; red[2][wid]=s2; }
    __syncthreads();
    if (tid < 3) {
        float s = bg2[tid];
        #pragma unroll
        for (int w = 0; w < 8; w++) s += red[tid][w];
        gl[tid] = s;
    }
    __syncthreads();
    float a0 = gl[0], a1 = gl[1], a2 = gl[2];
    float mx = fmaxf(a0, fmaxf(a1, a2));
    float e0 = __expf(a0-mx), e1 = __expf(a1-mx), e2 = __expf(a2-mx);
    float inv = 1.0f / (e0 + e1 + e2);
    e0 *= inv; e1 *= inv; e2 *= inv;
    const float4* f0 = (const float4*)(g_feats + (size_t)0*FEATSZ + (size_t)row*DD);
    const float4* f1 = (const float4*)(g_feats + (size_t)1*FEATSZ + (size_t)row*DD);
    const float4* f2 = (const float4*)(g_feats + (size_t)2*FEATSZ + (size_t)row*DD);
    float4* o4 = (float4*)(out + (size_t)row * DD);
    float4 v0 = f0[tid], v1 = f1[tid], v2 = f2[tid];
    o4[tid] = make_float4(e0*v0.x + e1*v1.x + e2*v2.x,
                          e0*v0.y + e1*v1.y + e2*v2.y,
                          e0*v0.z + e1*v1.z + e2*v2.z,
                          e0*v0.w + e1*v1.w + e2*v2.w);
}

// ---------------------------------------------------------------------------
// Launch
// ---------------------------------------------------------------------------
extern "C" void kernel_launch(void* const* d_in, const int* in_sizes, int n_in,
                              void* d_out, int out_size)
{
    const float* audio = (const float*)d_in[0];
    const float* video = (const float*)d_in[1];
    const float* image = (const float*)d_in[2];
    const float* Wq = (const float*)d_in[3];
    const float* Wk = (const float*)d_in[4];
    const float* Wv = (const float*)d_in[5];
    const float* Wp = (const float*)d_in[6];
    const float* bq = (const float*)d_in[7];
    const float* bk = (const float*)d_in[8];
    const float* bv = (const float*)d_in[9];
    const float* bp = (const float*)d_in[10];
    const float* qn = (const float*)d_in[11];
    const float* kn = (const float*)d_in[12];
    const float* rpb = (const float*)d_in[13];
    const float* Wg1 = (const float*)d_in[14];
    const float* bg1 = (const float*)d_in[15];
    const float* Wg2 = (const float*)d_in[16];
    const float* bg2 = (const float*)d_in[17];
    float* out = (float*)d_out;

    cudaFuncSetAttribute(tgemm_k<0>, cudaFuncAttributeMaxDynamicSharedMemorySize, SMEMB);
    cudaFuncSetAttribute(tgemm_k<1>, cudaFuncAttributeMaxDynamicSharedMemorySize, SMEMB);
    cudaFuncSetAttribute(tgemm_k<2>, cudaFuncAttributeMaxDynamicSharedMemorySize, SMEMB);
    cudaFuncSetAttribute(attn_mma_k, cudaFuncAttributeMaxDynamicSharedMemorySize, ASMEM);

    const float* qs[3] = {audio, video, image};
    const float* ks[3] = {video, audio, video};
    dim3 blk(256);
    dim3 gP(8, 32);

    transW_k<<<dim3(32, 32, 12), blk>>>(Wq, Wk, Wv, Wp);
    transG_k<<<dim3(64, 96), blk>>>(Wg1);

    for (int j = 0; j < 3; j++) {
        size_t oq = (size_t)j * DD * DD;
        size_t ok = (size_t)(3 + j) * DD * DD;
        size_t ov = (size_t)(6 + j) * DD * DD;
        size_t op = (size_t)(9 + j) * DD * DD;
        tgemm_k<0><<<gP, blk, SMEMB>>>(qs[j], oq, bq + j*DD, nullptr, qn + j*HD, 0.125f, 0, DD);
        tgemm_k<0><<<gP, blk, SMEMB>>>(ks[j], ok, bk + j*DD, nullptr, kn + j*HD, 1.0f, 1, DD);
        tgemm_k<0><<<gP, blk, SMEMB>>>(ks[j], ov, bv + j*DD, nullptr, nullptr, 0.f, 2, DD);
        attn_mma_k<<<dim3(128, 4), blk, ASMEM>>>(rpb + j * 15 * HH);
        tgemm_k<1><<<gP, blk, SMEMB>>>(nullptr, op, bp + j*DD, qs[j], nullptr, 0.f, j, DD);
    }
    tgemm_k<2><<<dim3(16, 32), blk, SMEMB>>>(nullptr, (size_t)12 * DD * DD, bg1,
                                             nullptr, nullptr, 0.f, 0, K3D);
    gate_fuse_k<<<BTLR, 256>>>(Wg2, bg2, out);
}

// round 6
// speedup vs baseline: 2.8669x; 1.0629x over previous
#include <cuda_runtime.h>
#include <cuda_fp16.h>
#include <math.h>
#include <stdint.h>

#define BB 2
#define TT 32
#define LLE 64
#define DD 1024
#define HH 16
#define HD 64
#define NWIN 8
#define SSQ 512
#define AROWS 4096
#define TLTOK 2048
#define BTLR 4096
#define DG 2048
#define K3D 3072
#define FEATSZ ((size_t)BTLR * DD)

// GEMM smem: A/B, 2 buffers, 2 ktiles of [128 rows][12 u32]
#define GTILE (128 * 12)
#define GBUF  (2 * GTILE)
#define BOFF  (2 * GBUF)
#define GSMEMB (4 * GBUF * 4)     // 49152 B
#define ASMEM ((128 * 36 + 64 * 36 + 64 * 36) * 4)   // 36864 B

__device__ __half g_Q[(size_t)NWIN * HH * SSQ * HD];
__device__ __half g_K[(size_t)NWIN * HH * SSQ * HD];
__device__ __half g_Vt[(size_t)NWIN * HH * HD * SSQ];   // [bh][d][s]
__device__ float  g_O[(size_t)AROWS * DD];
__device__ float  g_feats[(size_t)3 * BTLR * DD];
__device__ float  g_G[(size_t)BTLR * DG];
__device__ __half g_Wh[(size_t)12 * DD * DD + (size_t)DG * K3D];

__device__ __forceinline__ float gelu_f(float x) {
    return 0.5f * x * (1.0f + erff(x * 0.70710678118654752440f));
}
__device__ __forceinline__ uint32_t pack2(float lo, float hi) {
    uint32_t u;
    asm("cvt.rn.f16x2.f32 %0, %1, %2;" : "=r"(u) : "f"(hi), "f"(lo));
    return u;
}
__device__ __forceinline__ void mma16(float* d, const uint32_t* a, const uint32_t* b) {
    asm volatile("mma.sync.aligned.m16n8k16.row.col.f32.f16.f16.f32 "
        "{%0,%1,%2,%3}, {%4,%5,%6,%7}, {%8,%9}, {%0,%1,%2,%3};"
        : "+f"(d[0]), "+f"(d[1]), "+f"(d[2]), "+f"(d[3])
        : "r"(a[0]), "r"(a[1]), "r"(a[2]), "r"(a[3]), "r"(b[0]), "r"(b[1]));
}

// ---------------- weight transposes -> fp16 [n][k] ----------------
__global__ __launch_bounds__(256) void transW_k(
    const float* __restrict__ Wq, const float* __restrict__ Wk,
    const float* __restrict__ Wv, const float* __restrict__ Wp)
{
    __shared__ float tile[32][33];
    const int z = blockIdx.z;
    const float* W = (z < 3) ? Wq + (size_t)z * DD * DD
                   : (z < 6) ? Wk + (size_t)(z - 3) * DD * DD
                   : (z < 9) ? Wv + (size_t)(z - 6) * DD * DD
                             : Wp + (size_t)(z - 9) * DD * DD;
    __half* Wt = g_Wh + (size_t)z * DD * DD;
    const int n0 = blockIdx.x << 5, k0 = blockIdx.y << 5;
    const int tx = threadIdx.x & 31, ty = threadIdx.x >> 5;
    #pragma unroll
    for (int j = 0; j < 32; j += 8)
        tile[ty + j][tx] = W[(size_t)(k0 + ty + j) * DD + n0 + tx];
    __syncthreads();
    const int tp = threadIdx.x & 15, nr = threadIdx.x >> 4;
    #pragma unroll
    for (int j = 0; j < 2; j++) {
        const int nn = nr + j * 16;
        __half2 hv = __floats2half2_rn(tile[2 * tp][nn], tile[2 * tp + 1][nn]);
        *(__half2*)(Wt + (size_t)(n0 + nn) * DD + k0 + 2 * tp) = hv;
    }
}
__global__ __launch_bounds__(256) void transG_k(const float* __restrict__ Wg1)
{
    __shared__ float tile[32][33];
    __half* Wt = g_Wh + (size_t)12 * DD * DD;
    const int n0 = blockIdx.x << 5, k0 = blockIdx.y << 5;
    const int tx = threadIdx.x & 31, ty = threadIdx.x >> 5;
    #pragma unroll
    for (int j = 0; j < 32; j += 8)
        tile[ty + j][tx] = Wg1[(size_t)(k0 + ty + j) * DG + n0 + tx];
    __syncthreads();
    const int tp = threadIdx.x & 15, nr = threadIdx.x >> 4;
    #pragma unroll
    for (int j = 0; j < 2; j++) {
        const int nn = nr + j * 16;
        __half2 hv = __floats2half2_rn(tile[2 * tp][nn], tile[2 * tp + 1][nn]);
        *(__half2*)(Wt + (size_t)(n0 + nn) * K3D + k0 + 2 * tp) = hv;
    }
}

// ---------------------------------------------------------------------------
// fp16 mma GEMM. Tile M=128 N=128, K-chunk=32 (2 ktiles of 16), dbl-buffered.
// MODE 0: QKV (roll-gathered A; +bias, fused RMS, fp16 scatter; V transposed)
// MODE 1: out-proj (A=g_O fp32; +bias +residual -> g_feats fp32)
// MODE 2: gate L1 (A=concat feats; gelu -> g_G fp32)
// ---------------------------------------------------------------------------
template<int MODE>
__global__ __launch_bounds__(256, 2) void tgemm_k(
    const float* __restrict__ A0, size_t wh_off,
    const float* __restrict__ bias, const float* __restrict__ resid,
    const float* __restrict__ nw, float nscale, int which, int K)
{
    extern __shared__ uint32_t smu[];

    const int tid = threadIdx.x;
    const int wid = tid >> 5, lane = tid & 31;
    const int warpm = wid & 3, warpn = wid >> 2;
    const int g = lane >> 2, t = lane & 3;
    const int m0 = blockIdx.y << 7, n0 = blockIdx.x << 7;
    const int ra = tid >> 1, ka = (tid & 1) << 4, ktp = tid & 1;

    size_t arow = 0;
    if (MODE == 0) {
        const int r = m0 + ra;
        const int bw = r >> 9, s = r & 511;
        const int b = bw >> 2, w = bw & 3;
        const int st = s >> 6, l = s & 63;
        const int tt = (w * 8 + st + 4) & 31;        // roll(-SH) gather
        arow = (size_t)((b * TT + tt) * LLE + l) << 10;
    } else {
        arow = (size_t)(m0 + ra) << 10;
    }
    const __half* Bw = g_Wh + wh_off + (size_t)(n0 + ra) * K + ka;
    const float* Am = (MODE == 0) ? A0 : g_O;

    uint4 pa[2], pb[2];
#define LOADG(kc) do {                                                            \
    const float* as_;                                                             \
    if (MODE == 2) {                                                              \
        const int kg_ = (kc) + ka;                                                \
        as_ = g_feats + (size_t)(kg_ >> 10) * FEATSZ + arow + (kg_ & 1023);       \
    } else {                                                                      \
        as_ = Am + arow + (kc) + ka;                                              \
    }                                                                             \
    _Pragma("unroll")                                                             \
    for (int u_ = 0; u_ < 2; u_++) {                                              \
        float4 f0_ = *(const float4*)(as_ + u_ * 8);                              \
        float4 f1_ = *(const float4*)(as_ + u_ * 8 + 4);                          \
        pa[u_] = make_uint4(pack2(f0_.x, f0_.y), pack2(f0_.z, f0_.w),             \
                            pack2(f1_.x, f1_.y), pack2(f1_.z, f1_.w));            \
    }                                                                             \
    pb[0] = *(const uint4*)(Bw + (kc));                                           \
    pb[1] = *(const uint4*)(Bw + (kc) + 8);                                       \
} while (0)
#define STOREG(bf_) do {                                                          \
    uint32_t* ap_ = smu + (bf_) * GBUF + ktp * GTILE + ra * 12;                   \
    *(uint4*)ap_ = pa[0]; *(uint4*)(ap_ + 4) = pa[1];                             \
    uint32_t* bp_ = smu + BOFF + (bf_) * GBUF + ktp * GTILE + ra * 12;            \
    *(uint4*)bp_ = pb[0]; *(uint4*)(bp_ + 4) = pb[1];                             \
} while (0)

    float acc[2][8][4];
    #pragma unroll
    for (int i = 0; i < 2; i++)
        #pragma unroll
        for (int j = 0; j < 8; j++)
            #pragma unroll
            for (int q = 0; q < 4; q++) acc[i][j][q] = 0.f;

    const int NC = K >> 5;
    LOADG(0);
    STOREG(0);
    __syncthreads();

    for (int c = 0; c < NC; c++) {
        if (c + 1 < NC) LOADG((c + 1) << 5);
        const uint32_t* as = smu + (c & 1) * GBUF;
        const uint32_t* bs = smu + BOFF + (c & 1) * GBUF;
        #pragma unroll
        for (int kt = 0; kt < 2; kt++) {
            const uint32_t* a_ = as + kt * GTILE;
            const uint32_t* b_ = bs + kt * GTILE;
            uint32_t af[2][4], bf[8][2];
            #pragma unroll
            for (int mi = 0; mi < 2; mi++) {
                const int mb = warpm * 32 + mi * 16;
                af[mi][0] = a_[(mb + g) * 12 + t];
                af[mi][1] = a_[(mb + 8 + g) * 12 + t];
                af[mi][2] = a_[(mb + g) * 12 + t + 4];
                af[mi][3] = a_[(mb + 8 + g) * 12 + t + 4];
            }
            #pragma unroll
            for (int ni = 0; ni < 8; ni++) {
                const int rb = (warpn * 64 + ni * 8 + g) * 12;
                bf[ni][0] = b_[rb + t];
                bf[ni][1] = b_[rb + t + 4];
            }
            #pragma unroll
            for (int mi = 0; mi < 2; mi++)
                #pragma unroll
                for (int ni = 0; ni < 8; ni++)
                    mma16(acc[mi][ni], af[mi], bf[ni]);
        }
        if (c + 1 < NC) STOREG((c + 1) & 1);
        __syncthreads();
    }

    // ---- epilogue ----
    float2 bz[8], nz[8];
    #pragma unroll
    for (int ni = 0; ni < 8; ni++)
        bz[ni] = *(const float2*)(bias + n0 + warpn * 64 + ni * 8 + 2 * t);
    if (MODE == 0 && nw) {
        #pragma unroll
        for (int ni = 0; ni < 8; ni++)
            nz[ni] = *(const float2*)(nw + ni * 8 + 2 * t);
    }

    #pragma unroll
    for (int mi = 0; mi < 2; mi++)
    #pragma unroll
    for (int rh = 0; rh < 2; rh++) {
        const int m = m0 + warpm * 32 + mi * 16 + rh * 8 + g;
        float v[16];
        #pragma unroll
        for (int ni = 0; ni < 8; ni++) {
            v[2*ni]   = acc[mi][ni][2*rh]   + bz[ni].x;
            v[2*ni+1] = acc[mi][ni][2*rh+1] + bz[ni].y;
        }
        if (MODE == 0) {
            const int bw = m >> 9, s = m & 511;
            const int h = (n0 + warpn * 64) >> 6;
            if (nw) {
                float ss = 0.f;
                #pragma unroll
                for (int j = 0; j < 16; j++) ss = fmaf(v[j], v[j], ss);
                ss += __shfl_xor_sync(0xffffffffu, ss, 1);
                ss += __shfl_xor_sync(0xffffffffu, ss, 2);
                const float rs = rsqrtf(ss * (1.f / 64.f) + 1e-6f) * nscale;
                #pragma unroll
                for (int ni = 0; ni < 8; ni++) {
                    v[2*ni]   *= rs * nz[ni].x;
                    v[2*ni+1] *= rs * nz[ni].y;
                }
            }
            if (which == 2) {   // V: transposed fp16 store [bh][d][s]
                #pragma unroll
                for (int ni = 0; ni < 8; ni++) {
                    const int d = ni * 8 + 2 * t;
                    size_t base = (((size_t)(bw * HH + h) * 64 + d) << 9) + s;
                    g_Vt[base]       = __float2half_rn(v[2*ni]);
                    g_Vt[base + 512] = __float2half_rn(v[2*ni+1]);
                }
            } else {
                uint32_t* Cp = (uint32_t*)((which == 0) ? g_Q : g_K);
                const size_t rowb = (((size_t)(bw * HH + h) * 512 + s)) * 32;
                #pragma unroll
                for (int ni = 0; ni < 8; ni++)
                    Cp[rowb + ni * 4 + t] = pack2(v[2*ni], v[2*ni+1]);
            }
        } else if (MODE == 1) {
            const int bw = m >> 9, s = m & 511;
            const int b = bw >> 2, w = bw & 3;
            const int st = s >> 6, l = s & 63;
            const int tg = (w * 8 + st + 4) & 31;    // roll(+SH) scatter
            const float* rr = resid + ((size_t)((b * TT + tg) * LLE + l) << 10)
                            + n0 + warpn * 64 + 2 * t;
            float* fp = g_feats + (size_t)which * FEATSZ
                      + ((size_t)(b * TLTOK + tg * LLE + l) << 10)
                      + n0 + warpn * 64 + 2 * t;
            #pragma unroll
            for (int ni = 0; ni < 8; ni++) {
                float2 r2 = *(const float2*)(rr + ni * 8);
                *(float2*)(fp + ni * 8) = make_float2(v[2*ni] + r2.x, v[2*ni+1] + r2.y);
            }
        } else {
            float* gp = g_G + (size_t)m * DG + n0 + warpn * 64 + 2 * t;
            #pragma unroll
            for (int ni = 0; ni < 8; ni++)
                *(float2*)(gp + ni * 8) = make_float2(gelu_f(v[2*ni]), gelu_f(v[2*ni+1]));
        }
    }
}

// ---------------------------------------------------------------------------
// Flash attention, fp16 mma m16n8k16, fp32 softmax.
// Smem u32: QP[128][36] (Q then P), Kt[64][36], Vts[64][36].
// ---------------------------------------------------------------------------
__global__ __launch_bounds__(256, 2) void attn_mma_k(const float* __restrict__ rpb)
{
    extern __shared__ uint32_t sma[];
    uint32_t* QP  = sma;
    uint32_t* Kt  = sma + 128 * 36;
    uint32_t* Vts = Kt + 64 * 36;

    const int tid = threadIdx.x;
    const int wid = tid >> 5, lane = tid & 31;
    const int g = lane >> 2, t = lane & 3;
    const int bh = blockIdx.x, qt = blockIdx.y;
    const int h = bh & 15, bw = bh >> 4;
    const int q0 = qt << 7;
    const int tq = (qt << 1) + (wid >> 2);
    const int mrow = wid << 4;

    {   // stage Q (fp16 rows, 32 u32 each)
        const int r = tid >> 1, cu = (tid & 1) << 4;
        const uint32_t* qs = (const uint32_t*)g_Q + ((size_t)(bh * 512 + q0 + r)) * 32 + cu;
        #pragma unroll
        for (int u = 0; u < 4; u++)
            *(uint4*)&QP[r * 36 + cu + u * 4] = *(const uint4*)(qs + u * 4);
    }
    __syncthreads();

    uint32_t af[4][4];
    #pragma unroll
    for (int kt4 = 0; kt4 < 4; kt4++) {
        const int base = (mrow + g) * 36 + kt4 * 8;
        af[kt4][0] = QP[base + t];
        af[kt4][1] = QP[base + 8 * 36 + t];
        af[kt4][2] = QP[base + t + 4];
        af[kt4][3] = QP[base + 8 * 36 + t + 4];
    }
    __syncthreads();

    float oc[8][4];
    #pragma unroll
    for (int i = 0; i < 8; i++)
        #pragma unroll
        for (int q = 0; q < 4; q++) oc[i][q] = 0.f;
    float m_i[2] = {-1e30f, -1e30f}, l_i[2] = {0.f, 0.f};

    const int sr = tid >> 2, scu = (tid & 3) << 3;

    for (int kt = 0; kt < 8; kt++) {
        const float bias_s = rpb[(tq - kt + 7) * HH + h];
        {   // stage K [key][d] and V^T [d][key] (both fp16, direct copies)
            const uint32_t* ks = (const uint32_t*)g_K
                + ((size_t)(bh * 512 + kt * 64 + sr)) * 32 + scu;
            *(uint4*)&Kt[sr * 36 + scu]     = *(const uint4*)ks;
            *(uint4*)&Kt[sr * 36 + scu + 4] = *(const uint4*)(ks + 4);
            const uint32_t* vs = (const uint32_t*)g_Vt
                + ((size_t)(bh * 64 + sr)) * 256 + kt * 32 + scu;
            *(uint4*)&Vts[sr * 36 + scu]     = *(const uint4*)vs;
            *(uint4*)&Vts[sr * 36 + scu + 4] = *(const uint4*)(vs + 4);
        }
        __syncthreads();

        // S = Q K^T
        float sc[8][4];
        #pragma unroll
        for (int i = 0; i < 8; i++)
            #pragma unroll
            for (int q = 0; q < 4; q++) sc[i][q] = 0.f;
        #pragma unroll
        for (int kt4 = 0; kt4 < 4; kt4++) {
            #pragma unroll
            for (int ni = 0; ni < 8; ni++) {
                const int rb = (ni * 8 + g) * 36 + kt4 * 8;
                uint32_t bf[2] = { Kt[rb + t], Kt[rb + t + 4] };
                mma16(sc[ni], af[kt4], bf);
            }
        }

        // online softmax; P -> QP as fp16x2
        #pragma unroll
        for (int hr = 0; hr < 2; hr++) {
            float mx = -1e30f;
            #pragma unroll
            for (int ni = 0; ni < 8; ni++)
                mx = fmaxf(mx, fmaxf(sc[ni][2*hr], sc[ni][2*hr+1]));
            mx += bias_s;
            mx = fmaxf(mx, __shfl_xor_sync(0xffffffffu, mx, 1));
            mx = fmaxf(mx, __shfl_xor_sync(0xffffffffu, mx, 2));
            const float mn = fmaxf(m_i[hr], mx);
            const float fac = __expf(m_i[hr] - mn);
            m_i[hr] = mn;
            float sum = 0.f;
            const int prow = (mrow + hr * 8 + g) * 36;
            #pragma unroll
            for (int ni = 0; ni < 8; ni++) {
                float p0 = __expf(sc[ni][2*hr]   + bias_s - mn);
                float p1 = __expf(sc[ni][2*hr+1] + bias_s - mn);
                sum += p0 + p1;
                QP[prow + ni * 4 + t] = pack2(p0, p1);
            }
            sum += __shfl_xor_sync(0xffffffffu, sum, 1);
            sum += __shfl_xor_sync(0xffffffffu, sum, 2);
            l_i[hr] = l_i[hr] * fac + sum;
            #pragma unroll
            for (int ni = 0; ni < 8; ni++) {
                oc[ni][2*hr]   *= fac;
                oc[ni][2*hr+1] *= fac;
            }
        }
        __syncwarp();   // P is warp-private

        // O += P V
        #pragma unroll
        for (int kp = 0; kp < 4; kp++) {
            const int pb = (mrow + g) * 36 + kp * 8;
            uint32_t pf[4] = { QP[pb + t], QP[pb + 8 * 36 + t],
                               QP[pb + t + 4], QP[pb + 8 * 36 + t + 4] };
            #pragma unroll
            for (int ni = 0; ni < 8; ni++) {
                const int vr = (ni * 8 + g) * 36 + kp * 8;
                uint32_t vf[2] = { Vts[vr + t], Vts[vr + t + 4] };
                mma16(oc[ni], pf, vf);
            }
        }
        __syncthreads();
    }

    const float inv0 = 1.0f / l_i[0], inv1 = 1.0f / l_i[1];
    #pragma unroll
    for (int hr = 0; hr < 2; hr++) {
        const float inv = hr ? inv1 : inv0;
        const int row = q0 + mrow + hr * 8 + g;
        float* dst = g_O + ((size_t)(bw * SSQ + row)) * DD + h * HD + 2 * t;
        #pragma unroll
        for (int ni = 0; ni < 8; ni++)
            *(float2*)(dst + ni * 8) = make_float2(oc[ni][2*hr] * inv,
                                                   oc[ni][2*hr+1] * inv);
    }
}

// ---------------------------------------------------------------------------
// Gate logits + softmax + fuse.
// ---------------------------------------------------------------------------
__global__ __launch_bounds__(256) void gate_fuse_k(const float* __restrict__ Wg2,
                                                   const float* __restrict__ bg2,
                                                   float* __restrict__ out)
{
    const int row = blockIdx.x, tid = threadIdx.x;
    const float* g = g_G + (size_t)row * DG;
    float s0 = 0.f, s1 = 0.f, s2 = 0.f;
    for (int k = tid; k < DG; k += 256) {
        float x = g[k];
        s0 = fmaf(x, Wg2[k*3+0], s0);
        s1 = fmaf(x, Wg2[k*3+1], s1);
        s2 = fmaf(x, Wg2[k*3+2], s2);
    }
    #pragma unroll
    for (int m = 16; m; m >>= 1) {
        s0 += __shfl_xor_sync(0xffffffffu, s0, m);
        s1 += __shfl_xor_sync(0xffffffffu, s1, m);
        s2 += __shfl_xor_sync(0xffffffffu, s2, m);
    }
    __shared__ float red[3][8];
    __shared__ float gl[3];
    int wid = tid >> 5, lane = tid & 31;
    if (lane == 0) { red[0][wid]=s0; red[1][wid]=s1; red[2][wid]=s2; }
    __syncthreads();
    if (tid < 3) {
        float s = bg2[tid];
        #pragma unroll
        for (int w = 0; w < 8; w++) s += red[tid][w];
        gl[tid] = s;
    }
    __syncthreads();
    float a0 = gl[0], a1 = gl[1], a2 = gl[2];
    float mx = fmaxf(a0, fmaxf(a1, a2));
    float e0 = __expf(a0-mx), e1 = __expf(a1-mx), e2 = __expf(a2-mx);
    float inv = 1.0f / (e0 + e1 + e2);
    e0 *= inv; e1 *= inv; e2 *= inv;
    const float4* f0 = (const float4*)(g_feats + (size_t)0*FEATSZ + (size_t)row*DD);
    const float4* f1 = (const float4*)(g_feats + (size_t)1*FEATSZ + (size_t)row*DD);
    const float4* f2 = (const float4*)(g_feats + (size_t)2*FEATSZ + (size_t)row*DD);
    float4* o4 = (float4*)(out + (size_t)row * DD);
    float4 v0 = f0[tid], v1 = f1[tid], v2 = f2[tid];
    o4[tid] = make_float4(e0*v0.x + e1*v1.x + e2*v2.x,
                          e0*v0.y + e1*v1.y + e2*v2.y,
                          e0*v0.z + e1*v1.z + e2*v2.z,
                          e0*v0.w + e1*v1.w + e2*v2.w);
}

// ---------------------------------------------------------------------------
// Launch
// ---------------------------------------------------------------------------
extern "C" void kernel_launch(void* const* d_in, const int* in_sizes, int n_in,
                              void* d_out, int out_size)
{
    const float* audio = (const float*)d_in[0];
    const float* video = (const float*)d_in[1];
    const float* image = (const float*)d_in[2];
    const float* Wq = (const float*)d_in[3];
    const float* Wk = (const float*)d_in[4];
    const float* Wv = (const float*)d_in[5];
    const float* Wp = (const float*)d_in[6];
    const float* bq = (const float*)d_in[7];
    const float* bk = (const float*)d_in[8];
    const float* bv = (const float*)d_in[9];
    const float* bp = (const float*)d_in[10];
    const float* qn = (const float*)d_in[11];
    const float* kn = (const float*)d_in[12];
    const float* rpb = (const float*)d_in[13];
    const float* Wg1 = (const float*)d_in[14];
    const float* bg1 = (const float*)d_in[15];
    const float* Wg2 = (const float*)d_in[16];
    const float* bg2 = (const float*)d_in[17];
    float* out = (float*)d_out;

    cudaFuncSetAttribute(tgemm_k<0>, cudaFuncAttributeMaxDynamicSharedMemorySize, GSMEMB);
    cudaFuncSetAttribute(tgemm_k<1>, cudaFuncAttributeMaxDynamicSharedMemorySize, GSMEMB);
    cudaFuncSetAttribute(tgemm_k<2>, cudaFuncAttributeMaxDynamicSharedMemorySize, GSMEMB);
    cudaFuncSetAttribute(attn_mma_k, cudaFuncAttributeMaxDynamicSharedMemorySize, ASMEM);

    const float* qs[3] = {audio, video, image};
    const float* ks[3] = {video, audio, video};
    dim3 blk(256);
    dim3 gP(8, 32);

    transW_k<<<dim3(32, 32, 12), blk>>>(Wq, Wk, Wv, Wp);
    transG_k<<<dim3(64, 96), blk>>>(Wg1);

    for (int j = 0; j < 3; j++) {
        size_t oq = (size_t)j * DD * DD;
        size_t ok = (size_t)(3 + j) * DD * DD;
        size_t ov = (size_t)(6 + j) * DD * DD;
        size_t op = (size_t)(9 + j) * DD * DD;
        tgemm_k<0><<<gP, blk, GSMEMB>>>(qs[j], oq, bq + j*DD, nullptr, qn + j*HD, 0.125f, 0, DD);
        tgemm_k<0><<<gP, blk, GSMEMB>>>(ks[j], ok, bk + j*DD, nullptr, kn + j*HD, 1.0f, 1, DD);
        tgemm_k<0><<<gP, blk, GSMEMB>>>(ks[j], ov, bv + j*DD, nullptr, nullptr, 0.f, 2, DD);
        attn_mma_k<<<dim3(128, 4), blk, ASMEM>>>(rpb + j * 15 * HH);
        tgemm_k<1><<<gP, blk, GSMEMB>>>(nullptr, op, bp + j*DD, qs[j], nullptr, 0.f, j, DD);
    }
    tgemm_k<2><<<dim3(16, 32), blk, GSMEMB>>>(nullptr, (size_t)12 * DD * DD, bg1,
                                              nullptr, nullptr, 0.f, 0, K3D);
    gate_fuse_k<<<BTLR, 256>>>(Wg2, bg2, out);
}

// round 7
// speedup vs baseline: 4.9006x; 1.7094x over previous
#include <cuda_runtime.h>
#include <cuda_fp16.h>
#include <math.h>
#include <stdint.h>

#define BB 2
#define TT 32
#define LLE 64
#define DD 1024
#define HH 16
#define HD 64
#define NWIN 8
#define SSQ 512
#define AROWS 4096
#define TLTOK 2048
#define BTLR 4096
#define DG 2048
#define K3D 3072
#define FEATSZ ((size_t)BTLR * DD)

#define GTILE (128 * 12)
#define GBUF  (2 * GTILE)
#define BOFF  (2 * GBUF)
#define GSMEMB (4 * GBUF * 4)     // 49152 B
#define ASMEM ((128 * 36 + 64 * 36 + 64 * 36) * 4)   // 36864 B

__device__ __half g_Q[(size_t)NWIN * HH * SSQ * HD];
__device__ __half g_K[(size_t)NWIN * HH * SSQ * HD];
__device__ __half g_Vt[(size_t)NWIN * HH * HD * SSQ];   // [bh][d][s]
__device__ float  g_O[(size_t)AROWS * DD];
__device__ float  g_feats[(size_t)3 * BTLR * DD];
__device__ float  g_G[(size_t)BTLR * DG];
__device__ __half g_Wh[(size_t)12 * DD * DD + (size_t)DG * K3D];

__device__ __forceinline__ float gelu_f(float x) {
    return 0.5f * x * (1.0f + erff(x * 0.70710678118654752440f));
}
__device__ __forceinline__ uint32_t pack2(float lo, float hi) {
    uint32_t u;
    asm("cvt.rn.f16x2.f32 %0, %1, %2;" : "=r"(u) : "f"(hi), "f"(lo));
    return u;
}
__device__ __forceinline__ uint32_t smem_u32(const void* p) {
    uint32_t a;
    asm("{ .reg .u64 t; cvta.to.shared.u64 t, %1; cvt.u32.u64 %0, t; }" : "=r"(a) : "l"(p));
    return a;
}
__device__ __forceinline__ void ldsm4(uint32_t* r, uint32_t sa) {
    asm volatile("ldmatrix.sync.aligned.m8n8.x4.shared.b16 {%0,%1,%2,%3}, [%4];"
        : "=r"(r[0]), "=r"(r[1]), "=r"(r[2]), "=r"(r[3]) : "r"(sa));
}
__device__ __forceinline__ void mma16(float* d, const uint32_t* a, const uint32_t* b) {
    asm volatile("mma.sync.aligned.m16n8k16.row.col.f32.f16.f16.f32 "
        "{%0,%1,%2,%3}, {%4,%5,%6,%7}, {%8,%9}, {%0,%1,%2,%3};"
        : "+f"(d[0]), "+f"(d[1]), "+f"(d[2]), "+f"(d[3])
        : "r"(a[0]), "r"(a[1]), "r"(a[2]), "r"(a[3]), "r"(b[0]), "r"(b[1]));
}

// ---------------- weight transposes -> fp16 [n][k] ----------------
__global__ __launch_bounds__(256) void transW_k(
    const float* __restrict__ Wq, const float* __restrict__ Wk,
    const float* __restrict__ Wv, const float* __restrict__ Wp)
{
    __shared__ float tile[32][33];
    const int z = blockIdx.z;
    const float* W = (z < 3) ? Wq + (size_t)z * DD * DD
                   : (z < 6) ? Wk + (size_t)(z - 3) * DD * DD
                   : (z < 9) ? Wv + (size_t)(z - 6) * DD * DD
                             : Wp + (size_t)(z - 9) * DD * DD;
    __half* Wt = g_Wh + (size_t)z * DD * DD;
    const int n0 = blockIdx.x << 5, k0 = blockIdx.y << 5;
    const int tx = threadIdx.x & 31, ty = threadIdx.x >> 5;
    #pragma unroll
    for (int j = 0; j < 32; j += 8)
        tile[ty + j][tx] = W[(size_t)(k0 + ty + j) * DD + n0 + tx];
    __syncthreads();
    const int tp = threadIdx.x & 15, nr = threadIdx.x >> 4;
    #pragma unroll
    for (int j = 0; j < 2; j++) {
        const int nn = nr + j * 16;
        __half2 hv = __floats2half2_rn(tile[2 * tp][nn], tile[2 * tp + 1][nn]);
        *(__half2*)(Wt + (size_t)(n0 + nn) * DD + k0 + 2 * tp) = hv;
    }
}
__global__ __launch_bounds__(256) void transG_k(const float* __restrict__ Wg1)
{
    __shared__ float tile[32][33];
    __half* Wt = g_Wh + (size_t)12 * DD * DD;
    const int n0 = blockIdx.x << 5, k0 = blockIdx.y << 5;
    const int tx = threadIdx.x & 31, ty = threadIdx.x >> 5;
    #pragma unroll
    for (int j = 0; j < 32; j += 8)
        tile[ty + j][tx] = Wg1[(size_t)(k0 + ty + j) * DG + n0 + tx];
    __syncthreads();
    const int tp = threadIdx.x & 15, nr = threadIdx.x >> 4;
    #pragma unroll
    for (int j = 0; j < 2; j++) {
        const int nn = nr + j * 16;
        __half2 hv = __floats2half2_rn(tile[2 * tp][nn], tile[2 * tp + 1][nn]);
        *(__half2*)(Wt + (size_t)(n0 + nn) * K3D + k0 + 2 * tp) = hv;
    }
}

// ---------------------------------------------------------------------------
// fp16 mma GEMM with ldmatrix fragment loads.
// ---------------------------------------------------------------------------
template<int MODE>
__global__ __launch_bounds__(256, 2) void tgemm_k(
    const float* __restrict__ A0, size_t wh_off,
    const float* __restrict__ bias, const float* __restrict__ resid,
    const float* __restrict__ nw, float nscale, int which, int K)
{
    extern __shared__ uint32_t smu[];
    const uint32_t sb = smem_u32(smu);

    const int tid = threadIdx.x;
    const int wid = tid >> 5, lane = tid & 5*6+1; // placeholder avoided
    const int ln = tid & 31;
    const int warpm = wid & 3, warpn = wid >> 2;
    const int g = ln >> 2, t = ln & 3;
    const int m0 = blockIdx.y << 7, n0 = blockIdx.x << 7;
    const int ra = tid >> 1, ka = (tid & 1) << 4, ktp = tid & 1;

    // ldmatrix per-lane offsets (bytes, within one ktile buffer)
    const int arow_l = ((ln >> 3) & 1) * 8 + (ln & 7);
    const int akh = ln >> 4;
    int aoff[2];
    #pragma unroll
    for (int mi = 0; mi < 2; mi++)
        aoff[mi] = (((warpm * 32 + mi * 16 + arow_l) * 12) + akh * 4) << 2;
    const int brow_l = ((ln >> 4) * 8) + (ln & 7);
    const int bkh = (ln >> 3) & 1;
    int boff[4];
    #pragma unroll
    for (int pi = 0; pi < 4; pi++)
        boff[pi] = (((warpn * 64 + pi * 16 + brow_l) * 12) + bkh * 4) << 2;

    size_t arow = 0;
    if (MODE == 0) {
        const int r = m0 + ra;
        const int bw = r >> 9, s = r & 511;
        const int b = bw >> 2, w = bw & 3;
        const int st = s >> 6, l = s & 63;
        const int tt = (w * 8 + st + 4) & 31;        // roll(-SH) gather
        arow = (size_t)((b * TT + tt) * LLE + l) << 10;
    } else {
        arow = (size_t)(m0 + ra) << 10;
    }
    const __half* Bw = g_Wh + wh_off + (size_t)(n0 + ra) * K + ka;
    const float* Am = (MODE == 0) ? A0 : g_O;

    uint4 pa[2], pb[2];
#define LOADG(kc) do {                                                            \
    const float* as_;                                                             \
    if (MODE == 2) {                                                              \
        const int kg_ = (kc) + ka;                                                \
        as_ = g_feats + (size_t)(kg_ >> 10) * FEATSZ + arow + (kg_ & 1023);       \
    } else {                                                                      \
        as_ = Am + arow + (kc) + ka;                                              \
    }                                                                             \
    _Pragma("unroll")                                                             \
    for (int u_ = 0; u_ < 2; u_++) {                                              \
        float4 f0_ = *(const float4*)(as_ + u_ * 8);                              \
        float4 f1_ = *(const float4*)(as_ + u_ * 8 + 4);                          \
        pa[u_] = make_uint4(pack2(f0_.x, f0_.y), pack2(f0_.z, f0_.w),             \
                            pack2(f1_.x, f1_.y), pack2(f1_.z, f1_.w));            \
    }                                                                             \
    pb[0] = *(const uint4*)(Bw + (kc));                                           \
    pb[1] = *(const uint4*)(Bw + (kc) + 8);                                       \
} while (0)
#define STOREG(bf_) do {                                                          \
    uint32_t* ap_ = smu + (bf_) * GBUF + ktp * GTILE + ra * 12;                   \
    *(uint4*)ap_ = pa[0]; *(uint4*)(ap_ + 4) = pa[1];                             \
    uint32_t* bp_ = smu + BOFF + (bf_) * GBUF + ktp * GTILE + ra * 12;            \
    *(uint4*)bp_ = pb[0]; *(uint4*)(bp_ + 4) = pb[1];                             \
} while (0)

    float acc[2][8][4];
    #pragma unroll
    for (int i = 0; i < 2; i++)
        #pragma unroll
        for (int j = 0; j < 8; j++)
            #pragma unroll
            for (int q = 0; q < 4; q++) acc[i][j][q] = 0.f;

    const int NC = K >> 5;
    LOADG(0);
    STOREG(0);
    __syncthreads();

    for (int c = 0; c < NC; c++) {
        if (c + 1 < NC) LOADG((c + 1) << 5);
        const uint32_t bsel = (c & 1) * GBUF;
        #pragma unroll
        for (int kt = 0; kt < 2; kt++) {
            const uint32_t ab = sb + ((bsel + kt * GTILE) << 2);
            const uint32_t bb = sb + ((BOFF + bsel + kt * GTILE) << 2);
            uint32_t af[2][4], bfr[4][4];
            ldsm4(af[0], ab + aoff[0]);
            ldsm4(af[1], ab + aoff[1]);
            #pragma unroll
            for (int pi = 0; pi < 4; pi++)
                ldsm4(bfr[pi], bb + boff[pi]);
            #pragma unroll
            for (int mi = 0; mi < 2; mi++)
                #pragma unroll
                for (int ni = 0; ni < 8; ni++)
                    mma16(acc[mi][ni], af[mi], &bfr[ni >> 1][(ni & 1) * 2]);
        }
        if (c + 1 < NC) STOREG((c + 1) & 1);
        __syncthreads();
    }

    // ---- epilogue ----
    float2 bz[8], nz[8];
    #pragma unroll
    for (int ni = 0; ni < 8; ni++)
        bz[ni] = *(const float2*)(bias + n0 + warpn * 64 + ni * 8 + 2 * t);
    if (MODE == 0 && nw) {
        #pragma unroll
        for (int ni = 0; ni < 8; ni++)
            nz[ni] = *(const float2*)(nw + ni * 8 + 2 * t);
    }

    #pragma unroll
    for (int mi = 0; mi < 2; mi++)
    #pragma unroll
    for (int rh = 0; rh < 2; rh++) {
        const int m = m0 + warpm * 32 + mi * 16 + rh * 8 + g;
        float v[16];
        #pragma unroll
        for (int ni = 0; ni < 8; ni++) {
            v[2*ni]   = acc[mi][ni][2*rh]   + bz[ni].x;
            v[2*ni+1] = acc[mi][ni][2*rh+1] + bz[ni].y;
        }
        if (MODE == 0) {
            const int bw = m >> 9, s = m & 511;
            const int h = (n0 + warpn * 64) >> 6;
            if (nw) {
                float ss = 0.f;
                #pragma unroll
                for (int j = 0; j < 16; j++) ss = fmaf(v[j], v[j], ss);
                ss += __shfl_xor_sync(0xffffffffu, ss, 1);
                ss += __shfl_xor_sync(0xffffffffu, ss, 2);
                const float rs = rsqrtf(ss * (1.f / 64.f) + 1e-6f) * nscale;
                #pragma unroll
                for (int ni = 0; ni < 8; ni++) {
                    v[2*ni]   *= rs * nz[ni].x;
                    v[2*ni+1] *= rs * nz[ni].y;
                }
            }
            if (which == 2) {   // V: transposed fp16 store [bh][d][s]
                #pragma unroll
                for (int ni = 0; ni < 8; ni++) {
                    const int d = ni * 8 + 2 * t;
                    size_t base = (((size_t)(bw * HH + h) * 64 + d) << 9) + s;
                    g_Vt[base]       = __float2half_rn(v[2*ni]);
                    g_Vt[base + 512] = __float2half_rn(v[2*ni+1]);
                }
            } else {
                uint32_t* Cp = (uint32_t*)((which == 0) ? g_Q : g_K);
                const size_t rowb = (((size_t)(bw * HH + h) * 512 + s)) * 32;
                #pragma unroll
                for (int ni = 0; ni < 8; ni++)
                    Cp[rowb + ni * 4 + t] = pack2(v[2*ni], v[2*ni+1]);
            }
        } else if (MODE == 1) {
            const int bw = m >> 9, s = m & 511;
            const int b = bw >> 2, w = bw & 3;
            const int st = s >> 6, l = s & 63;
            const int tg = (w * 8 + st + 4) & 31;    // roll(+SH) scatter
            const float* rr = resid + ((size_t)((b * TT + tg) * LLE + l) << 10)
                            + n0 + warpn * 64 + 2 * t;
            float* fp = g_feats + (size_t)which * FEATSZ
                      + ((size_t)(b * TLTOK + tg * LLE + l) << 10)
                      + n0 + warpn * 64 + 2 * t;
            #pragma unroll
            for (int ni = 0; ni < 8; ni++) {
                float2 r2 = *(const float2*)(rr + ni * 8);
                *(float2*)(fp + ni * 8) = make_float2(v[2*ni] + r2.x, v[2*ni+1] + r2.y);
            }
        } else {
            float* gp = g_G + (size_t)m * DG + n0 + warpn * 64 + 2 * t;
            #pragma unroll
            for (int ni = 0; ni < 8; ni++)
                *(float2*)(gp + ni * 8) = make_float2(gelu_f(v[2*ni]), gelu_f(v[2*ni+1]));
        }
    }
}

// ---------------------------------------------------------------------------
// Flash attention, fp16 mma + ldmatrix, fp32 softmax.
// ---------------------------------------------------------------------------
__global__ __launch_bounds__(256, 2) void attn_mma_k(const float* __restrict__ rpb)
{
    extern __shared__ uint32_t sma[];
    uint32_t* QP  = sma;
    uint32_t* Kt  = sma + 128 * 36;
    uint32_t* Vts = Kt + 64 * 36;
    const uint32_t qb_sa = smem_u32(QP);
    const uint32_t kb_sa = smem_u32(Kt);
    const uint32_t vb_sa = smem_u32(Vts);

    const int tid = threadIdx.x;
    const int wid = tid >> 5, ln = tid & 31;
    const int g = ln >> 2, t = ln & 3;
    const int bh = blockIdx.x, qt = blockIdx.y;
    const int h = bh & 15, bw = bh >> 4;
    const int q0 = qt << 7;
    const int tq = (qt << 1) + (wid >> 2);
    const int mrow = wid << 4;

    // ldmatrix lane offsets (bytes), row stride 36 u32
    const int arow_l = ((ln >> 3) & 1) * 8 + (ln & 7);
    const int akh = ln >> 4;
    const int aoff = ((mrow + arow_l) * 36 + akh * 4) << 2;       // A-type rows at mrow
    const int brow_l = ((ln >> 4) * 8) + (ln & 7);
    const int bkh = (ln >> 3) & 1;
    int boff[4];
    #pragma unroll
    for (int pi = 0; pi < 4; pi++)
        boff[pi] = ((pi * 16 + brow_l) * 36 + bkh * 4) << 2;      // B-type rows 0..63

    {   // stage Q
        const int r = tid >> 1, cu = (tid & 1) << 4;
        const uint32_t* qs = (const uint32_t*)g_Q + ((size_t)(bh * 512 + q0 + r)) * 32 + cu;
        #pragma unroll
        for (int u = 0; u < 4; u++)
            *(uint4*)&QP[r * 36 + cu + u * 4] = *(const uint4*)(qs + u * 4);
    }
    __syncthreads();

    uint32_t af[4][4];
    #pragma unroll
    for (int kt4 = 0; kt4 < 4; kt4++)
        ldsm4(af[kt4], qb_sa + aoff + (kt4 << 5));
    __syncthreads();

    float oc[8][4];
    #pragma unroll
    for (int i = 0; i < 8; i++)
        #pragma unroll
        for (int q = 0; q < 4; q++) oc[i][q] = 0.f;
    float m_i[2] = {-1e30f, -1e30f}, l_i[2] = {0.f, 0.f};

    const int sr = tid >> 2, scu = (tid & 3) << 3;

    for (int kt = 0; kt < 8; kt++) {
        const float bias_s = rpb[(tq - kt + 7) * HH + h];
        {   // stage K [key][d] and V^T [d][key]
            const uint32_t* ks = (const uint32_t*)g_K
                + ((size_t)(bh * 512 + kt * 64 + sr)) * 32 + scu;
            *(uint4*)&Kt[sr * 36 + scu]     = *(const uint4*)ks;
            *(uint4*)&Kt[sr * 36 + scu + 4] = *(const uint4*)(ks + 4);
            const uint32_t* vs = (const uint32_t*)g_Vt
                + ((size_t)(bh * 64 + sr)) * 256 + kt * 32 + scu;
            *(uint4*)&Vts[sr * 36 + scu]     = *(const uint4*)vs;
            *(uint4*)&Vts[sr * 36 + scu + 4] = *(const uint4*)(vs + 4);
        }
        __syncthreads();

        // S = Q K^T
        float sc[8][4];
        #pragma unroll
        for (int i = 0; i < 8; i++)
            #pragma unroll
            for (int q = 0; q < 4; q++) sc[i][q] = 0.f;
        #pragma unroll
        for (int kt4 = 0; kt4 < 4; kt4++) {
            uint32_t bfr[4][4];
            #pragma unroll
            for (int pi = 0; pi < 4; pi++)
                ldsm4(bfr[pi], kb_sa + boff[pi] + (kt4 << 5));
            #pragma unroll
            for (int ni = 0; ni < 8; ni++)
                mma16(sc[ni], af[kt4], &bfr[ni >> 1][(ni & 1) * 2]);
        }

        // online softmax; P -> QP as fp16x2
        #pragma unroll
        for (int hr = 0; hr < 2; hr++) {
            float mx = -1e30f;
            #pragma unroll
            for (int ni = 0; ni < 8; ni++)
                mx = fmaxf(mx, fmaxf(sc[ni][2*hr], sc[ni][2*hr+1]));
            mx += bias_s;
            mx = fmaxf(mx, __shfl_xor_sync(0xffffffffu, mx, 1));
            mx = fmaxf(mx, __shfl_xor_sync(0xffffffffu, mx, 2));
            const float mn = fmaxf(m_i[hr], mx);
            const float fac = __expf(m_i[hr] - mn);
            m_i[hr] = mn;
            float sum = 0.f;
            const int prow = (mrow + hr * 8 + g) * 36;
            #pragma unroll
            for (int ni = 0; ni < 8; ni++) {
                float p0 = __expf(sc[ni][2*hr]   + bias_s - mn);
                float p1 = __expf(sc[ni][2*hr+1] + bias_s - mn);
                sum += p0 + p1;
                QP[prow + ni * 4 + t] = pack2(p0, p1);
            }
            sum += __shfl_xor_sync(0xffffffffu, sum, 1);
            sum += __shfl_xor_sync(0xffffffffu, sum, 2);
            l_i[hr] = l_i[hr] * fac + sum;
            #pragma unroll
            for (int ni = 0; ni < 8; ni++) {
                oc[ni][2*hr]   *= fac;
                oc[ni][2*hr+1] *= fac;
            }
        }
        __syncwarp();   // P is warp-private

        // O += P V
        #pragma unroll
        for (int kp = 0; kp < 4; kp++) {
            uint32_t pf[4], vfr[4][4];
            ldsm4(pf, qb_sa + aoff + (kp << 5));
            #pragma unroll
            for (int pi = 0; pi < 4; pi++)
                ldsm4(vfr[pi], vb_sa + boff[pi] + (kp << 5));
            #pragma unroll
            for (int ni = 0; ni < 8; ni++)
                mma16(oc[ni], pf, &vfr[ni >> 1][(ni & 1) * 2]);
        }
        __syncthreads();
    }

    const float inv0 = 1.0f / l_i[0], inv1 = 1.0f / l_i[1];
    #pragma unroll
    for (int hr = 0; hr < 2; hr++) {
        const float inv = hr ? inv1 : inv0;
        const int row = q0 + mrow + hr * 8 + g;
        float* dst = g_O + ((size_t)(bw * SSQ + row)) * DD + h * HD + 2 * t;
        #pragma unroll
        for (int ni = 0; ni < 8; ni++)
            *(float2*)(dst + ni * 8) = make_float2(oc[ni][2*hr] * inv,
                                                   oc[ni][2*hr+1] * inv);
    }
}

// ---------------------------------------------------------------------------
// Gate logits + softmax + fuse.
// ---------------------------------------------------------------------------
__global__ __launch_bounds__(256) void gate_fuse_k(const float* __restrict__ Wg2,
                                                   const float* __restrict__ bg2,
                                                   float* __restrict__ out)
{
    const int row = blockIdx.x, tid = threadIdx.x;
    const float* g = g_G + (size_t)row * DG;
    float s0 = 0.f, s1 = 0.f, s2 = 0.f;
    for (int k = tid; k < DG; k += 256) {
        float x = g[k];
        s0 = fmaf(x, Wg2[k*3+0], s0);
        s1 = fmaf(x, Wg2[k*3+1], s1);
        s2 = fmaf(x, Wg2[k*3+2], s2);
    }
    #pragma unroll
    for (int m = 16; m; m >>= 1) {
        s0 += __shfl_xor_sync(0xffffffffu, s0, m);
        s1 += __shfl_xor_sync(0xffffffffu, s1, m);
        s2 += __shfl_xor_sync(0xffffffffu, s2, m);
    }
    __shared__ float red[3][8];
    __shared__ float gl[3];
    int wid = tid >> 5, lane = tid & 31;
    if (lane == 0) { red[0][wid]=s0; red[1][wid]=s1; red[2][wid]=s2; }
    __syncthreads();
    if (tid < 3) {
        float s = bg2[tid];
        #pragma unroll
        for (int w = 0; w < 8; w++) s += red[tid][w];
        gl[tid] = s;
    }
    __syncthreads();
    float a0 = gl[0], a1 = gl[1], a2 = gl[2];
    float mx = fmaxf(a0, fmaxf(a1, a2));
    float e0 = __expf(a0-mx), e1 = __expf(a1-mx), e2 = __expf(a2-mx);
    float inv = 1.0f / (e0 + e1 + e2);
    e0 *= inv; e1 *= inv; e2 *= inv;
    const float4* f0 = (const float4*)(g_feats + (size_t)0*FEATSZ + (size_t)row*DD);
    const float4* f1 = (const float4*)(g_feats + (size_t)1*FEATSZ + (size_t)row*DD);
    const float4* f2 = (const float4*)(g_feats + (size_t)2*FEATSZ + (size_t)row*DD);
    float4* o4 = (float4*)(out + (size_t)row * DD);
    float4 v0 = f0[tid], v1 = f1[tid], v2 = f2[tid];
    o4[tid] = make_float4(e0*v0.x + e1*v1.x + e2*v2.x,
                          e0*v0.y + e1*v1.y + e2*v2.y,
                          e0*v0.z + e1*v1.z + e2*v2.z,
                          e0*v0.w + e1*v1.w + e2*v2.w);
}

// ---------------------------------------------------------------------------
// Launch
// ---------------------------------------------------------------------------
extern "C" void kernel_launch(void* const* d_in, const int* in_sizes, int n_in,
                              void* d_out, int out_size)
{
    const float* audio = (const float*)d_in[0];
    const float* video = (const float*)d_in[1];
    const float* image = (const float*)d_in[2];
    const float* Wq = (const float*)d_in[3];
    const float* Wk = (const float*)d_in[4];
    const float* Wv = (const float*)d_in[5];
    const float* Wp = (const float*)d_in[6];
    const float* bq = (const float*)d_in[7];
    const float* bk = (const float*)d_in[8];
    const float* bv = (const float*)d_in[9];
    const float* bp = (const float*)d_in[10];
    const float* qn = (const float*)d_in[11];
    const float* kn = (const float*)d_in[12];
    const float* rpb = (const float*)d_in[13];
    const float* Wg1 = (const float*)d_in[14];
    const float* bg1 = (const float*)d_in[15];
    const float* Wg2 = (const float*)d_in[16];
    const float* bg2 = (const float*)d_in[17];
    float* out = (float*)d_out;

    cudaFuncSetAttribute(tgemm_k<0>, cudaFuncAttributeMaxDynamicSharedMemorySize, GSMEMB);
    cudaFuncSetAttribute(tgemm_k<1>, cudaFuncAttributeMaxDynamicSharedMemorySize, GSMEMB);
    cudaFuncSetAttribute(tgemm_k<2>, cudaFuncAttributeMaxDynamicSharedMemorySize, GSMEMB);
    cudaFuncSetAttribute(attn_mma_k, cudaFuncAttributeMaxDynamicSharedMemorySize, ASMEM);

    const float* qs[3] = {audio, video, image};
    const float* ks[3] = {video, audio, video};
    dim3 blk(256);
    dim3 gP(8, 32);

    transW_k<<<dim3(32, 32, 12), blk>>>(Wq, Wk, Wv, Wp);
    transG_k<<<dim3(64, 96), blk>>>(Wg1);

    for (int j = 0; j < 3; j++) {
        size_t oq = (size_t)j * DD * DD;
        size_t ok = (size_t)(3 + j) * DD * DD;
        size_t ov = (size_t)(6 + j) * DD * DD;
        size_t op = (size_t)(9 + j) * DD * DD;
        tgemm_k<0><<<gP, blk, GSMEMB>>>(qs[j], oq, bq + j*DD, nullptr, qn + j*HD, 0.125f, 0, DD);
        tgemm_k<0><<<gP, blk, GSMEMB>>>(ks[j], ok, bk + j*DD, nullptr, kn + j*HD, 1.0f, 1, DD);
        tgemm_k<0><<<gP, blk, GSMEMB>>>(ks[j], ov, bv + j*DD, nullptr, nullptr, 0.f, 2, DD);
        attn_mma_k<<<dim3(128, 4), blk, ASMEM>>>(rpb + j * 15 * HH);
        tgemm_k<1><<<gP, blk, GSMEMB>>>(nullptr, op, bp + j*DD, qs[j], nullptr, 0.f, j, DD);
    }
    tgemm_k<2><<<dim3(16, 32), blk, GSMEMB>>>(nullptr, (size_t)12 * DD * DD, bg1,
                                              nullptr, nullptr, 0.f, 0, K3D);
    gate_fuse_k<<<BTLR, 256>>>(Wg2, bg2, out);
}

// round 8
// speedup vs baseline: 5.2485x; 1.0710x over previous
#include <cuda_runtime.h>
#include <cuda_fp16.h>
#include <math.h>
#include <stdint.h>

#define BB 2
#define TT 32
#define LLE 64
#define DD 1024
#define HH 16
#define HD 64
#define NWIN 8
#define SSQ 512
#define AROWS 4096
#define TLTOK 2048
#define BTLR 4096
#define DG 2048
#define K3D 3072
#define FEATSZ ((size_t)BTLR * DD)

// GEMM smem (u32 units): A 2 ktiles x 256 rows x 12, B 2 ktiles x 128 x 12
#define AKT 3072
#define ABUF (2 * AKT)
#define BKT 1536
#define BBUF (2 * BKT)
#define BOFFU (2 * ABUF)
#define GSMEMB ((BOFFU + 2 * BBUF) * 4)   // 73728 B
#define ASMEM ((128 * 36 + 64 * 36 + 64 * 36) * 4)   // 36864 B

__device__ __half g_Q[(size_t)NWIN * HH * SSQ * HD];
__device__ __half g_K[(size_t)NWIN * HH * SSQ * HD];
__device__ __half g_Vt[(size_t)NWIN * HH * HD * SSQ];   // [bh][d][s]
__device__ __half g_Oh[(size_t)AROWS * DD];
__device__ __half g_Xh[(size_t)3 * BTLR * DD];          // fp16 modalities
__device__ float  g_feats[(size_t)3 * BTLR * DD];
__device__ __half g_featsh[(size_t)3 * BTLR * DD];
__device__ float  g_G[(size_t)BTLR * DG];
__device__ __half g_Wh[(size_t)12 * DD * DD + (size_t)DG * K3D];

__device__ __forceinline__ float gelu_f(float x) {
    return 0.5f * x * (1.0f + erff(x * 0.70710678118654752440f));
}
__device__ __forceinline__ uint32_t pack2(float lo, float hi) {
    uint32_t u;
    asm("cvt.rn.f16x2.f32 %0, %1, %2;" : "=r"(u) : "f"(hi), "f"(lo));
    return u;
}
__device__ __forceinline__ uint32_t smem_u32(const void* p) {
    uint32_t a;
    asm("{ .reg .u64 t; cvta.to.shared.u64 t, %1; cvt.u32.u64 %0, t; }" : "=r"(a) : "l"(p));
    return a;
}
__device__ __forceinline__ void ldsm4(uint32_t* r, uint32_t sa) {
    asm volatile("ldmatrix.sync.aligned.m8n8.x4.shared.b16 {%0,%1,%2,%3}, [%4];"
        : "=r"(r[0]), "=r"(r[1]), "=r"(r[2]), "=r"(r[3]) : "r"(sa));
}
__device__ __forceinline__ void mma16(float* d, const uint32_t* a, const uint32_t* b) {
    asm volatile("mma.sync.aligned.m16n8k16.row.col.f32.f16.f16.f32 "
        "{%0,%1,%2,%3}, {%4,%5,%6,%7}, {%8,%9}, {%0,%1,%2,%3};"
        : "+f"(d[0]), "+f"(d[1]), "+f"(d[2]), "+f"(d[3])
        : "r"(a[0]), "r"(a[1]), "r"(a[2]), "r"(a[3]), "r"(b[0]), "r"(b[1]));
}

// ---------------- prepass: modalities fp32 -> fp16 ----------------
__global__ __launch_bounds__(256) void conv_k(
    const float* __restrict__ a, const float* __restrict__ v,
    const float* __restrict__ im)
{
    const float* src = (blockIdx.y == 0) ? a : (blockIdx.y == 1) ? v : im;
    __half* dst = g_Xh + (size_t)blockIdx.y * FEATSZ;
    const size_t i = ((size_t)blockIdx.x * 256 + threadIdx.x) * 8;
    float4 f0 = *(const float4*)(src + i);
    float4 f1 = *(const float4*)(src + i + 4);
    uint4 o = make_uint4(pack2(f0.x, f0.y), pack2(f0.z, f0.w),
                         pack2(f1.x, f1.y), pack2(f1.z, f1.w));
    *(uint4*)(dst + i) = o;
}

// ---------------- weight transposes -> fp16 [n][k] ----------------
__global__ __launch_bounds__(256) void transW_k(
    const float* __restrict__ Wq, const float* __restrict__ Wk,
    const float* __restrict__ Wv, const float* __restrict__ Wp)
{
    __shared__ float tile[32][33];
    const int z = blockIdx.z;
    const float* W = (z < 3) ? Wq + (size_t)z * DD * DD
                   : (z < 6) ? Wk + (size_t)(z - 3) * DD * DD
                   : (z < 9) ? Wv + (size_t)(z - 6) * DD * DD
                             : Wp + (size_t)(z - 9) * DD * DD;
    __half* Wt = g_Wh + (size_t)z * DD * DD;
    const int n0 = blockIdx.x << 5, k0 = blockIdx.y << 5;
    const int tx = threadIdx.x & 31, ty = threadIdx.x >> 5;
    #pragma unroll
    for (int j = 0; j < 32; j += 8)
        tile[ty + j][tx] = W[(size_t)(k0 + ty + j) * DD + n0 + tx];
    __syncthreads();
    const int tp = threadIdx.x & 15, nr = threadIdx.x >> 4;
    #pragma unroll
    for (int j = 0; j < 2; j++) {
        const int nn = nr + j * 16;
        __half2 hv = __floats2half2_rn(tile[2 * tp][nn], tile[2 * tp + 1][nn]);
        *(__half2*)(Wt + (size_t)(n0 + nn) * DD + k0 + 2 * tp) = hv;
    }
}
__global__ __launch_bounds__(256) void transG_k(const float* __restrict__ Wg1)
{
    __shared__ float tile[32][33];
    __half* Wt = g_Wh + (size_t)12 * DD * DD;
    const int n0 = blockIdx.x << 5, k0 = blockIdx.y << 5;
    const int tx = threadIdx.x & 31, ty = threadIdx.x >> 5;
    #pragma unroll
    for (int j = 0; j < 32; j += 8)
        tile[ty + j][tx] = Wg1[(size_t)(k0 + ty + j) * DG + n0 + tx];
    __syncthreads();
    const int tp = threadIdx.x & 15, nr = threadIdx.x >> 4;
    #pragma unroll
    for (int j = 0; j < 2; j++) {
        const int nn = nr + j * 16;
        __half2 hv = __floats2half2_rn(tile[2 * tp][nn], tile[2 * tp + 1][nn]);
        *(__half2*)(Wt + (size_t)(n0 + nn) * K3D + k0 + 2 * tp) = hv;
    }
}

// ---------------------------------------------------------------------------
// fp16 mma GEMM: CTA tile M=256 N=128, warp tile 64x64 (8 warps 4x2),
// K-chunk 32 (2 ktiles), double-buffered, ldmatrix fragments, fp16 A loads.
// ---------------------------------------------------------------------------
template<int MODE>
__global__ __launch_bounds__(256) void tgemm_k(
    const __half* __restrict__ A0h, size_t wh_off,
    const float* __restrict__ bias, const float* __restrict__ resid,
    const float* __restrict__ nw, float nscale, int which, int K)
{
    extern __shared__ uint32_t smu[];
    const uint32_t sb = smem_u32(smu);

    const int tid = threadIdx.x;
    const int wid = tid >> 5, ln = tid & 31;
    const int warpm = wid & 3, warpn = wid >> 2;
    const int g = ln >> 2, t = ln & 3;
    const int m0 = blockIdx.y << 8, n0 = blockIdx.x << 7;
    const int rab = tid >> 1, ktp = tid & 1;        // B staging

    // ldmatrix lane offsets (bytes, within one ktile buffer)
    const int arow_l = ((ln >> 3) & 1) * 8 + (ln & 7);
    const int akh = ln >> 4;
    int aoff[4];
    #pragma unroll
    for (int mi = 0; mi < 4; mi++)
        aoff[mi] = (((warpm * 64 + mi * 16 + arow_l) * 12) + akh * 4) << 2;
    const int brow_l = ((ln >> 4) * 8) + (ln & 7);
    const int bkh = (ln >> 3) & 1;
    int boff[4];
    #pragma unroll
    for (int pi = 0; pi < 4; pi++)
        boff[pi] = (((warpn * 64 + pi * 16 + brow_l) * 12) + bkh * 4) << 2;

    size_t arow = 0;
    if (MODE == 0) {
        const int r = m0 + tid;
        const int bw = r >> 9, s = r & 511;
        const int b = bw >> 2, w = bw & 3;
        const int st = s >> 6, l = s & 63;
        const int tt = (w * 8 + st + 4) & 31;        // roll(-SH) gather
        arow = (size_t)((b * TT + tt) * LLE + l) << 10;
    } else {
        arow = (size_t)(m0 + tid) << 10;
    }
    const __half* Bw = g_Wh + wh_off + (size_t)(n0 + rab) * K + ((tid & 1) << 4);
    const __half* Am = (MODE == 0) ? A0h : g_Oh;

    uint4 pa[4], pb[2];
#define LOADG(kc) do {                                                            \
    const __half* as_;                                                            \
    if (MODE == 2) {                                                              \
        as_ = g_featsh + (size_t)((kc) >> 10) * FEATSZ + arow + ((kc) & 1023);    \
    } else {                                                                      \
        as_ = Am + arow + (kc);                                                   \
    }                                                                             \
    _Pragma("unroll")                                                             \
    for (int u_ = 0; u_ < 4; u_++) pa[u_] = *(const uint4*)(as_ + u_ * 8);        \
    pb[0] = *(const uint4*)(Bw + (kc));                                           \
    pb[1] = *(const uint4*)(Bw + (kc) + 8);                                       \
} while (0)
#define STOREG(bf_) do {                                                          \
    uint32_t* a0_ = smu + (bf_) * ABUF + tid * 12;                                \
    *(uint4*)a0_ = pa[0]; *(uint4*)(a0_ + 4) = pa[1];                             \
    uint32_t* a1_ = a0_ + AKT;                                                    \
    *(uint4*)a1_ = pa[2]; *(uint4*)(a1_ + 4) = pa[3];                             \
    uint32_t* b0_ = smu + BOFFU + (bf_) * BBUF + ktp * BKT + rab * 12;            \
    *(uint4*)b0_ = pb[0]; *(uint4*)(b0_ + 4) = pb[1];                             \
} while (0)

    float acc[4][8][4];
    #pragma unroll
    for (int i = 0; i < 4; i++)
        #pragma unroll
        for (int j = 0; j < 8; j++)
            #pragma unroll
            for (int q = 0; q < 4; q++) acc[i][j][q] = 0.f;

    const int NC = K >> 5;
    LOADG(0);
    STOREG(0);
    __syncthreads();

    for (int c = 0; c < NC; c++) {
        if (c + 1 < NC) LOADG((c + 1) << 5);
        const int bsel = c & 1;
        #pragma unroll
        for (int kt = 0; kt < 2; kt++) {
            const uint32_t ab = sb + ((bsel * ABUF + kt * AKT) << 2);
            const uint32_t bb = sb + ((BOFFU + bsel * BBUF + kt * BKT) << 2);
            uint32_t af[4][4], bfr[4][4];
            #pragma unroll
            for (int mi = 0; mi < 4; mi++)
                ldsm4(af[mi], ab + aoff[mi]);
            #pragma unroll
            for (int pi = 0; pi < 4; pi++)
                ldsm4(bfr[pi], bb + boff[pi]);
            #pragma unroll
            for (int mi = 0; mi < 4; mi++)
                #pragma unroll
                for (int ni = 0; ni < 8; ni++)
                    mma16(acc[mi][ni], af[mi], &bfr[ni >> 1][(ni & 1) * 2]);
        }
        if (c + 1 < NC) STOREG((c + 1) & 1);
        __syncthreads();
    }

    // ---- epilogue ----
    float2 bz[8], nz[8];
    #pragma unroll
    for (int ni = 0; ni < 8; ni++)
        bz[ni] = *(const float2*)(bias + n0 + warpn * 64 + ni * 8 + 2 * t);
    if (MODE == 0 && nw) {
        #pragma unroll
        for (int ni = 0; ni < 8; ni++)
            nz[ni] = *(const float2*)(nw + ni * 8 + 2 * t);
    }

    #pragma unroll
    for (int mi = 0; mi < 4; mi++)
    #pragma unroll
    for (int rh = 0; rh < 2; rh++) {
        const int m = m0 + warpm * 64 + mi * 16 + rh * 8 + g;
        float v[16];
        #pragma unroll
        for (int ni = 0; ni < 8; ni++) {
            v[2*ni]   = acc[mi][ni][2*rh]   + bz[ni].x;
            v[2*ni+1] = acc[mi][ni][2*rh+1] + bz[ni].y;
        }
        if (MODE == 0) {
            const int bw = m >> 9, s = m & 511;
            const int h = (n0 + warpn * 64) >> 6;
            if (nw) {
                float ss = 0.f;
                #pragma unroll
                for (int j = 0; j < 16; j++) ss = fmaf(v[j], v[j], ss);
                ss += __shfl_xor_sync(0xffffffffu, ss, 1);
                ss += __shfl_xor_sync(0xffffffffu, ss, 2);
                const float rs = rsqrtf(ss * (1.f / 64.f) + 1e-6f) * nscale;
                #pragma unroll
                for (int ni = 0; ni < 8; ni++) {
                    v[2*ni]   *= rs * nz[ni].x;
                    v[2*ni+1] *= rs * nz[ni].y;
                }
            }
            if (which == 2) {   // V: transposed fp16 store [bh][d][s]
                #pragma unroll
                for (int ni = 0; ni < 8; ni++) {
                    const int d = ni * 8 + 2 * t;
                    size_t base = (((size_t)(bw * HH + h) * 64 + d) << 9) + s;
                    g_Vt[base]       = __float2half_rn(v[2*ni]);
                    g_Vt[base + 512] = __float2half_rn(v[2*ni+1]);
                }
            } else {
                uint32_t* Cp = (uint32_t*)((which == 0) ? g_Q : g_K);
                const size_t rowb = (((size_t)(bw * HH + h) * 512 + s)) * 32;
                #pragma unroll
                for (int ni = 0; ni < 8; ni++)
                    Cp[rowb + ni * 4 + t] = pack2(v[2*ni], v[2*ni+1]);
            }
        } else if (MODE == 1) {
            const int bw = m >> 9, s = m & 511;
            const int b = bw >> 2, w = bw & 3;
            const int st = s >> 6, l = s & 63;
            const int tg = (w * 8 + st + 4) & 31;    // roll(+SH) scatter
            const size_t rowo = ((size_t)(b * TLTOK + tg * LLE + l) << 10)
                              + n0 + warpn * 64 + 2 * t;
            const float* rr = resid + ((size_t)((b * TT + tg) * LLE + l) << 10)
                            + n0 + warpn * 64 + 2 * t;
            float* fp = g_feats + (size_t)which * FEATSZ + rowo;
            uint32_t* fh = (uint32_t*)(g_featsh + (size_t)which * FEATSZ + rowo);
            #pragma unroll
            for (int ni = 0; ni < 8; ni++) {
                float2 r2 = *(const float2*)(rr + ni * 8);
                float2 o2 = make_float2(v[2*ni] + r2.x, v[2*ni+1] + r2.y);
                *(float2*)(fp + ni * 8) = o2;
                fh[ni * 4] = pack2(o2.x, o2.y);
            }
        } else {
            float* gp = g_G + (size_t)m * DG + n0 + warpn * 64 + 2 * t;
            #pragma unroll
            for (int ni = 0; ni < 8; ni++)
                *(float2*)(gp + ni * 8) = make_float2(gelu_f(v[2*ni]), gelu_f(v[2*ni+1]));
        }
    }
}

// ---------------------------------------------------------------------------
// Flash attention, fp16 mma + ldmatrix, fp32 softmax; fp16 output to g_Oh.
// ---------------------------------------------------------------------------
__global__ __launch_bounds__(256, 2) void attn_mma_k(const float* __restrict__ rpb)
{
    extern __shared__ uint32_t sma[];
    uint32_t* QP  = sma;
    uint32_t* Kt  = sma + 128 * 36;
    uint32_t* Vts = Kt + 64 * 36;
    const uint32_t qb_sa = smem_u32(QP);
    const uint32_t kb_sa = smem_u32(Kt);
    const uint32_t vb_sa = smem_u32(Vts);

    const int tid = threadIdx.x;
    const int wid = tid >> 5, ln = tid & 31;
    const int g = ln >> 2, t = ln & 3;
    const int bh = blockIdx.x, qt = blockIdx.y;
    const int h = bh & 15, bw = bh >> 4;
    const int q0 = qt << 7;
    const int tq = (qt << 1) + (wid >> 2);
    const int mrow = wid << 4;

    const int arow_l = ((ln >> 3) & 1) * 8 + (ln & 7);
    const int akh = ln >> 4;
    const int aoff = ((mrow + arow_l) * 36 + akh * 4) << 2;
    const int brow_l = ((ln >> 4) * 8) + (ln & 7);
    const int bkh = (ln >> 3) & 1;
    int boff[4];
    #pragma unroll
    for (int pi = 0; pi < 4; pi++)
        boff[pi] = ((pi * 16 + brow_l) * 36 + bkh * 4) << 2;

    {   // stage Q
        const int r = tid >> 1, cu = (tid & 1) << 4;
        const uint32_t* qs = (const uint32_t*)g_Q + ((size_t)(bh * 512 + q0 + r)) * 32 + cu;
        #pragma unroll
        for (int u = 0; u < 4; u++)
            *(uint4*)&QP[r * 36 + cu + u * 4] = *(const uint4*)(qs + u * 4);
    }
    __syncthreads();

    uint32_t af[4][4];
    #pragma unroll
    for (int kt4 = 0; kt4 < 4; kt4++)
        ldsm4(af[kt4], qb_sa + aoff + (kt4 << 5));
    __syncthreads();

    float oc[8][4];
    #pragma unroll
    for (int i = 0; i < 8; i++)
        #pragma unroll
        for (int q = 0; q < 4; q++) oc[i][q] = 0.f;
    float m_i[2] = {-1e30f, -1e30f}, l_i[2] = {0.f, 0.f};

    const int sr = tid >> 2, scu = (tid & 3) << 3;

    for (int kt = 0; kt < 8; kt++) {
        const float bias_s = rpb[(tq - kt + 7) * HH + h];
        {   // stage K [key][d] and V^T [d][key]
            const uint32_t* ks = (const uint32_t*)g_K
                + ((size_t)(bh * 512 + kt * 64 + sr)) * 32 + scu;
            *(uint4*)&Kt[sr * 36 + scu]     = *(const uint4*)ks;
            *(uint4*)&Kt[sr * 36 + scu + 4] = *(const uint4*)(ks + 4);
            const uint32_t* vs = (const uint32_t*)g_Vt
                + ((size_t)(bh * 64 + sr)) * 256 + kt * 32 + scu;
            *(uint4*)&Vts[sr * 36 + scu]     = *(const uint4*)vs;
            *(uint4*)&Vts[sr * 36 + scu + 4] = *(const uint4*)(vs + 4);
        }
        __syncthreads();

        float sc[8][4];
        #pragma unroll
        for (int i = 0; i < 8; i++)
            #pragma unroll
            for (int q = 0; q < 4; q++) sc[i][q] = 0.f;
        #pragma unroll
        for (int kt4 = 0; kt4 < 4; kt4++) {
            uint32_t bfr[4][4];
            #pragma unroll
            for (int pi = 0; pi < 4; pi++)
                ldsm4(bfr[pi], kb_sa + boff[pi] + (kt4 << 5));
            #pragma unroll
            for (int ni = 0; ni < 8; ni++)
                mma16(sc[ni], af[kt4], &bfr[ni >> 1][(ni & 1) * 2]);
        }

        #pragma unroll
        for (int hr = 0; hr < 2; hr++) {
            float mx = -1e30f;
            #pragma unroll
            for (int ni = 0; ni < 8; ni++)
                mx = fmaxf(mx, fmaxf(sc[ni][2*hr], sc[ni][2*hr+1]));
            mx += bias_s;
            mx = fmaxf(mx, __shfl_xor_sync(0xffffffffu, mx, 1));
            mx = fmaxf(mx, __shfl_xor_sync(0xffffffffu, mx, 2));
            const float mn = fmaxf(m_i[hr], mx);
            const float fac = __expf(m_i[hr] - mn);
            m_i[hr] = mn;
            float sum = 0.f;
            const int prow = (mrow + hr * 8 + g) * 36;
            #pragma unroll
            for (int ni = 0; ni < 8; ni++) {
                float p0 = __expf(sc[ni][2*hr]   + bias_s - mn);
                float p1 = __expf(sc[ni][2*hr+1] + bias_s - mn);
                sum += p0 + p1;
                QP[prow + ni * 4 + t] = pack2(p0, p1);
            }
            sum += __shfl_xor_sync(0xffffffffu, sum, 1);
            sum += __shfl_xor_sync(0xffffffffu, sum, 2);
            l_i[hr] = l_i[hr] * fac + sum;
            #pragma unroll
            for (int ni = 0; ni < 8; ni++) {
                oc[ni][2*hr]   *= fac;
                oc[ni][2*hr+1] *= fac;
            }
        }
        __syncwarp();

        #pragma unroll
        for (int kp = 0; kp < 4; kp++) {
            uint32_t pf[4], vfr[4][4];
            ldsm4(pf, qb_sa + aoff + (kp << 5));
            #pragma unroll
            for (int pi = 0; pi < 4; pi++)
                ldsm4(vfr[pi], vb_sa + boff[pi] + (kp << 5));
            #pragma unroll
            for (int ni = 0; ni < 8; ni++)
                mma16(oc[ni], pf, &vfr[ni >> 1][(ni & 1) * 2]);
        }
        __syncthreads();
    }

    const float inv0 = 1.0f / l_i[0], inv1 = 1.0f / l_i[1];
    #pragma unroll
    for (int hr = 0; hr < 2; hr++) {
        const float inv = hr ? inv1 : inv0;
        const int row = q0 + mrow + hr * 8 + g;
        uint32_t* dst = (uint32_t*)g_Oh + ((size_t)(bw * SSQ + row)) * 512 + h * 32 + t;
        #pragma unroll
        for (int ni = 0; ni < 8; ni++)
            dst[ni * 4] = pack2(oc[ni][2*hr] * inv, oc[ni][2*hr+1] * inv);
    }
}

// ---------------------------------------------------------------------------
// Gate logits + softmax + fuse.
// ---------------------------------------------------------------------------
__global__ __launch_bounds__(256) void gate_fuse_k(const float* __restrict__ Wg2,
                                                   const float* __restrict__ bg2,
                                                   float* __restrict__ out)
{
    const int row = blockIdx.x, tid = threadIdx.x;
    const float* g = g_G + (size_t)row * DG;
    float s0 = 0.f, s1 = 0.f, s2 = 0.f;
    for (int k = tid; k < DG; k += 256) {
        float x = g[k];
        s0 = fmaf(x, Wg2[k*3+0], s0);
        s1 = fmaf(x, Wg2[k*3+1], s1);
        s2 = fmaf(x, Wg2[k*3+2], s2);
    }
    #pragma unroll
    for (int m = 16; m; m >>= 1) {
        s0 += __shfl_xor_sync(0xffffffffu, s0, m);
        s1 += __shfl_xor_sync(0xffffffffu, s1, m);
        s2 += __shfl_xor_sync(0xffffffffu, s2, m);
    }
    __shared__ float red[3][8];
    __shared__ float gl[3];
    int wid = tid >> 5, lane = tid & 31;
    if (lane == 0) { red[0][wid]=s0; red[1][wid]=s1; red[2][wid]=s2; }
    __syncthreads();
    if (tid < 3) {
        float s = bg2[tid];
        #pragma unroll
        for (int w = 0; w < 8; w++) s += red[tid][w];
        gl[tid] = s;
    }
    __syncthreads();
    float a0 = gl[0], a1 = gl[1], a2 = gl[2];
    float mx = fmaxf(a0, fmaxf(a1, a2));
    float e0 = __expf(a0-mx), e1 = __expf(a1-mx), e2 = __expf(a2-mx);
    float inv = 1.0f / (e0 + e1 + e2);
    e0 *= inv; e1 *= inv; e2 *= inv;
    const float4* f0 = (const float4*)(g_feats + (size_t)0*FEATSZ + (size_t)row*DD);
    const float4* f1 = (const float4*)(g_feats + (size_t)1*FEATSZ + (size_t)row*DD);
    const float4* f2 = (const float4*)(g_feats + (size_t)2*FEATSZ + (size_t)row*DD);
    float4* o4 = (float4*)(out + (size_t)row * DD);
    float4 v0 = f0[tid], v1 = f1[tid], v2 = f2[tid];
    o4[tid] = make_float4(e0*v0.x + e1*v1.x + e2*v2.x,
                          e0*v0.y + e1*v1.y + e2*v2.y,
                          e0*v0.z + e1*v1.z + e2*v2.z,
                          e0*v0.w + e1*v1.w + e2*v2.w);
}

// ---------------------------------------------------------------------------
// Launch
// ---------------------------------------------------------------------------
extern "C" void kernel_launch(void* const* d_in, const int* in_sizes, int n_in,
                              void* d_out, int out_size)
{
    const float* audio = (const float*)d_in[0];
    const float* video = (const float*)d_in[1];
    const float* image = (const float*)d_in[2];
    const float* Wq = (const float*)d_in[3];
    const float* Wk = (const float*)d_in[4];
    const float* Wv = (const float*)d_in[5];
    const float* Wp = (const float*)d_in[6];
    const float* bq = (const float*)d_in[7];
    const float* bk = (const float*)d_in[8];
    const float* bv = (const float*)d_in[9];
    const float* bp = (const float*)d_in[10];
    const float* qn = (const float*)d_in[11];
    const float* kn = (const float*)d_in[12];
    const float* rpb = (const float*)d_in[13];
    const float* Wg1 = (const float*)d_in[14];
    const float* bg1 = (const float*)d_in[15];
    const float* Wg2 = (const float*)d_in[16];
    const float* bg2 = (const float*)d_in[17];
    float* out = (float*)d_out;

    cudaFuncSetAttribute(tgemm_k<0>, cudaFuncAttributeMaxDynamicSharedMemorySize, GSMEMB);
    cudaFuncSetAttribute(tgemm_k<1>, cudaFuncAttributeMaxDynamicSharedMemorySize, GSMEMB);
    cudaFuncSetAttribute(tgemm_k<2>, cudaFuncAttributeMaxDynamicSharedMemorySize, GSMEMB);
    cudaFuncSetAttribute(attn_mma_k, cudaFuncAttributeMaxDynamicSharedMemorySize, ASMEM);

    __half* Xh_dev = nullptr;   // device-symbol offsets handled inside kernels
    (void)Xh_dev;

    dim3 blk(256);
    dim3 gP(8, 16);     // N=1024/128, M=4096/256

    conv_k<<<dim3(2048, 3), blk>>>(audio, video, image);
    transW_k<<<dim3(32, 32, 12), blk>>>(Wq, Wk, Wv, Wp);
    transG_k<<<dim3(64, 96), blk>>>(Wg1);

    // modality fp16 base offsets: audio=0, video=1, image=2
    const size_t xo[3] = {0, FEATSZ, 2 * FEATSZ};
    const int qsel[3] = {0, 1, 2};
    const int ksel[3] = {1, 0, 1};

    for (int j = 0; j < 3; j++) {
        size_t oq = (size_t)j * DD * DD;
        size_t ok = (size_t)(3 + j) * DD * DD;
        size_t ov = (size_t)(6 + j) * DD * DD;
        size_t op = (size_t)(9 + j) * DD * DD;
        __half* qAh; cudaGetSymbolAddress((void**)&qAh, g_Xh);
        const __half* qA = qAh + xo[qsel[j]];
        const __half* kA = qAh + xo[ksel[j]];
        const float* res = (j == 0) ? audio : (j == 1) ? video : image;
        tgemm_k<0><<<gP, blk, GSMEMB>>>(qA, oq, bq + j*DD, nullptr, qn + j*HD, 0.125f, 0, DD);
        tgemm_k<0><<<gP, blk, GSMEMB>>>(kA, ok, bk + j*DD, nullptr, kn + j*HD, 1.0f, 1, DD);
        tgemm_k<0><<<gP, blk, GSMEMB>>>(kA, ov, bv + j*DD, nullptr, nullptr, 0.f, 2, DD);
        attn_mma_k<<<dim3(128, 4), blk, ASMEM>>>(rpb + j * 15 * HH);
        tgemm_k<1><<<gP, blk, GSMEMB>>>(nullptr, op, bp + j*DD, res, nullptr, 0.f, j, DD);
    }
    tgemm_k<2><<<dim3(16, 16), blk, GSMEMB>>>(nullptr, (size_t)12 * DD * DD, bg1,
                                              nullptr, nullptr, 0.f, 0, K3D);
    gate_fuse_k<<<BTLR, 256>>>(Wg2, bg2, out);
}